// round 6
// baseline (speedup 1.0000x reference)
#include <cuda_runtime.h>
#include <cuda_fp16.h>
#include <cstdint>

// Problem constants
#define BB 4
#define SS 2048
#define DD 1024
#define HH 16
#define DHH 64
#define MTOT (BB*SS)     // 8192
#define NTOT (3*DD)      // 3072
#define KTOT (DD)        // 1024

#define QKVN ((size_t)BB*HH*SS*DHH)

// Q pre-scale: 1/sqrt(64) * log2(e)  (softmax done in exp2 space)
#define QSCALE 0.1803368801111204f

// Scratch: fp16 single-precision-pass operands
__device__ __align__(16) __half g_A[(size_t)MTOT*KTOT];   // x   [M, K] K-major
__device__ __align__(16) __half g_B[(size_t)NTOT*KTOT];   // W^T [N, K] K-major
__device__ __align__(16) __half g_Qh[QKVN];               // [B,H,S,64] (pre-scaled)
__device__ __align__(16) __half g_Kh[QKVN];               // [B,H,S,64]
__device__ __align__(16) __half g_Vh[QKVN];               // [B,H,64,S] (transposed)

// ---------------------------------------------------------------------------
// Helpers (sm_103 baseline-safe: ldmatrix / mma.sync / cp.async only)
// ---------------------------------------------------------------------------
__device__ __forceinline__ uint32_t smem_u32(const void* p) {
    uint32_t a;
    asm("{ .reg .u64 t; cvta.to.shared.u64 t, %1; cvt.u32.u64 %0, t; }" : "=r"(a) : "l"(p));
    return a;
}
__device__ __forceinline__ void ldm_x4(uint32_t* r, uint32_t addr) {
    asm volatile("ldmatrix.sync.aligned.m8n8.x4.shared.b16 {%0,%1,%2,%3}, [%4];"
        : "=r"(r[0]), "=r"(r[1]), "=r"(r[2]), "=r"(r[3]) : "r"(addr));
}
__device__ __forceinline__ void mma16816(float* d, const uint32_t* a, uint32_t b0, uint32_t b1) {
    asm volatile("mma.sync.aligned.m16n8k16.row.col.f32.f16.f16.f32 "
        "{%0,%1,%2,%3}, {%4,%5,%6,%7}, {%8,%9}, {%0,%1,%2,%3};"
        : "+f"(d[0]), "+f"(d[1]), "+f"(d[2]), "+f"(d[3])
        : "r"(a[0]), "r"(a[1]), "r"(a[2]), "r"(a[3]), "r"(b0), "r"(b1));
}
__device__ __forceinline__ void cp16(uint32_t dst, const void* src) {
    asm volatile("cp.async.cg.shared.global [%0], [%1], 16;" :: "r"(dst), "l"(src));
}
#define CP_COMMIT() asm volatile("cp.async.commit_group;" ::: "memory")
#define CP_WAIT1()  asm volatile("cp.async.wait_group 1;" ::: "memory")
#define CP_WAIT0()  asm volatile("cp.async.wait_group 0;" ::: "memory")

__device__ __forceinline__ uint32_t packhf(float e1, float e0) {
    uint32_t r; asm("cvt.rn.f16x2.f32 %0, %1, %2;" : "=r"(r) : "f"(e1), "f"(e0)); return r;
}

// ---------------------------------------------------------------------------
// Conversion: x [M,K] fp32 -> g_A fp16 (8 elements per thread)
// ---------------------------------------------------------------------------
__global__ __launch_bounds__(256) void conv_x_kernel(const float* __restrict__ x)
{
    const int base = (blockIdx.x * 256 + threadIdx.x) * 8;
    float4 v0 = *(const float4*)(x + base);
    float4 v1 = *(const float4*)(x + base + 4);
    __half h[8];
    h[0] = __float2half(v0.x); h[1] = __float2half(v0.y);
    h[2] = __float2half(v0.z); h[3] = __float2half(v0.w);
    h[4] = __float2half(v1.x); h[5] = __float2half(v1.y);
    h[6] = __float2half(v1.z); h[7] = __float2half(v1.w);
    *(float4*)(g_A + base) = *(float4*)h;
}

// ---------------------------------------------------------------------------
// Conversion: W [K,N] fp32 -> g_B [N,K] fp16 (transpose, 16B stores)
// ---------------------------------------------------------------------------
__global__ __launch_bounds__(256) void conv_w_kernel(const float* __restrict__ W)
{
    __shared__ float T[32][33];
    const int n0 = blockIdx.x * 32;
    const int k0 = blockIdx.y * 32;
    const int tid = threadIdx.x;
    const int tx = tid & 31, ty = tid >> 5;

    #pragma unroll
    for (int i = 0; i < 4; i++)
        T[ty + i * 8][tx] = W[(size_t)(k0 + ty + i * 8) * NTOT + n0 + tx];
    __syncthreads();

    if (tid < 128) {
        const int nl = tid >> 2;          // 0..31
        const int kq = (tid & 3) * 8;     // 0,8,16,24
        __half h[8];
        #pragma unroll
        for (int i = 0; i < 8; i++) h[i] = __float2half(T[kq + i][nl]);
        *(float4*)(g_B + (size_t)(n0 + nl) * KTOT + k0 + kq) = *(float4*)h;
    }
}

// ---------------------------------------------------------------------------
// HMMA GEMM: C[8192,3072] = A @ B^T. CTA 256x128, warp tile 64x64 (4x2 warps),
// BK=32, 3-stage cp.async. Epilogue: +bias -> fp16 Q(xQSCALE)/K/V^T.
// ---------------------------------------------------------------------------
#define ROWB 80
#define STG_BYTES ((256+128)*ROWB)   // 30720
#define GSTG 3
#define GEMM_SMEM (GSTG*STG_BYTES)   // 92160
#define A_ROWS 256
#define B_OFF (A_ROWS*ROWB)          // 20480

__device__ __forceinline__ void gemm_load_stage(uint32_t smb, int s, int kc,
                                                int m0, int n0, int tid)
{
    const uint32_t base = smb + s * STG_BYTES;
    #pragma unroll
    for (int i = 0; i < 6; i++) {
        const int idx = i * 256 + tid;        // 0..1535
        const int row = idx >> 2, c = idx & 3;
        if (row < A_ROWS) {
            cp16(base + row * ROWB + c * 16,
                 g_A + (size_t)(m0 + row) * KTOT + kc + c * 8);
        } else {
            const int br = row - A_ROWS;
            cp16(base + B_OFF + br * ROWB + c * 16,
                 g_B + (size_t)(n0 + br) * KTOT + kc + c * 8);
        }
    }
}

__global__ __launch_bounds__(256, 1) void qkv_gemm_hmma(const float* __restrict__ bias)
{
    extern __shared__ __align__(16) char sm[];
    const uint32_t smb = smem_u32(sm);
    const int tid = threadIdx.x, lane = tid & 31, wid = tid >> 5;
    const int m0 = blockIdx.y * 256;
    const int n0 = blockIdx.x * 128;
    const int wm = wid >> 1;   // 0..3 (64-row groups)
    const int wn = wid & 1;    // 0..1 (64-col groups)

    float acc[4][8][4];
    #pragma unroll
    for (int i = 0; i < 4; i++)
        #pragma unroll
        for (int j = 0; j < 8; j++)
            #pragma unroll
            for (int r = 0; r < 4; r++) acc[i][j][r] = 0.0f;

    gemm_load_stage(smb, 0, 0,  m0, n0, tid);
    CP_COMMIT();
    gemm_load_stage(smb, 1, 32, m0, n0, tid);
    CP_COMMIT();

    const int NIT = KTOT / 32;   // 32
    for (int it = 0; it < NIT; it++) {
        CP_WAIT1();
        __syncthreads();
        if (it + 2 < NIT)
            gemm_load_stage(smb, (it + 2) % GSTG, (it + 2) * 32, m0, n0, tid);
        CP_COMMIT();

        const uint32_t sb = smb + (it % GSTG) * STG_BYTES;
        #pragma unroll
        for (int ks = 0; ks < 2; ks++) {
            const uint32_t koff = (ks * 2 + (lane >> 4)) * 16;
            uint32_t a[4][4], b[4][4];
            #pragma unroll
            for (int mt = 0; mt < 4; mt++)
                ldm_x4(a[mt], sb + (wm * 64 + mt * 16 + (lane & 15)) * ROWB + koff);
            #pragma unroll
            for (int bt = 0; bt < 4; bt++)
                ldm_x4(b[bt], sb + B_OFF + (wn * 64 + bt * 16 + (lane & 15)) * ROWB + koff);
            #pragma unroll
            for (int mt = 0; mt < 4; mt++)
                #pragma unroll
                for (int nt = 0; nt < 8; nt++) {
                    const int bt = nt >> 1, sub = nt & 1;
                    mma16816(acc[mt][nt], a[mt], b[bt][sub], b[bt][sub + 2]);
                }
        }
    }

    // Epilogue: +bias, fp16, write Q (xQSCALE) / K (row-major) and V (transposed)
    #pragma unroll
    for (int mt = 0; mt < 4; mt++) {
        #pragma unroll
        for (int nt = 0; nt < 8; nt++) {
            const int m = m0 + wm * 64 + mt * 16 + (lane >> 2);
            const int n = n0 + wn * 64 + (nt >> 1) * 16 + (nt & 1) * 8 + 2 * (lane & 3);
            const float2 bb = *(const float2*)(bias + n);
            const int hh    = n / 192;
            const int which = (n >> 6) % 3;
            const int dh    = n & 63;
            const int bi = m >> 11, si = m & 2047;
            const int bh = bi * HH + hh;
            #pragma unroll
            for (int rr = 0; rr < 2; rr++) {
                const int s = si + rr * 8;
                float vx = acc[mt][nt][rr * 2 + 0] + bb.x;
                float vy = acc[mt][nt][rr * 2 + 1] + bb.y;
                if (which == 0) { vx *= QSCALE; vy *= QSCALE; }
                if (which == 2) {
                    const size_t vb = ((size_t)bh * DHH + dh) * SS + s;
                    g_Vh[vb]      = __float2half(vx);
                    g_Vh[vb + SS] = __float2half(vy);
                } else {
                    const size_t qb = ((size_t)bh * SS + s) * DHH + dh;
                    __half2 hv; hv.x = __float2half(vx); hv.y = __float2half(vy);
                    *(__half2*)(((which == 0) ? g_Qh : g_Kh) + qb) = hv;
                }
            }
        }
    }
}

// ---------------------------------------------------------------------------
// HMMA causal flash attention, fp16, exp2-space softmax.
// CTA: 128 q rows, 4 warps x 32 rows. K-tiles of 64 keys, double-buffered.
// ---------------------------------------------------------------------------
#define APITCH 144
#define AST 18432   // stage bytes: Kh@0, Vh@9216 (64 rows x 144B)
#define ATT_SMEM (2*AST)  // 36864

__global__ __launch_bounds__(128) void attn_hmma(float* __restrict__ out)
{
    extern __shared__ __align__(16) char sm[];
    const uint32_t smb = smem_u32(sm);
    const int tid = threadIdx.x, lane = tid & 31, w = tid >> 5;
    const int bh = blockIdx.y, qt = blockIdx.x;
    const int q0 = qt * 128;
    const int tg = lane & 3, g = lane >> 2;

    // --- stage Q tile, then ldmatrix into regs ---
    {
        const __half* qhg = g_Qh + ((size_t)bh * SS + q0) * DHH;
        #pragma unroll
        for (int i = 0; i < 8; i++) {
            const int idx = i * 128 + tid;
            const int row = idx >> 3, c = idx & 7;
            *(float4*)(sm + row * APITCH + c * 16) = *(const float4*)(qhg + row * 64 + c * 8);
        }
    }
    __syncthreads();
    uint32_t qh[2][4][4];
    #pragma unroll
    for (int mt = 0; mt < 2; mt++)
        #pragma unroll
        for (int kc = 0; kc < 4; kc++)
            ldm_x4(qh[mt][kc], smb + (w * 32 + mt * 16 + (lane & 15)) * APITCH
                              + (kc * 2 + (lane >> 4)) * 16);
    __syncthreads();

    float o[2][8][4];
    #pragma unroll
    for (int mt = 0; mt < 2; mt++)
        #pragma unroll
        for (int nt = 0; nt < 8; nt++)
            #pragma unroll
            for (int e = 0; e < 4; e++) o[mt][nt][e] = 0.0f;
    float mrow[2][2] = {{-1e30f, -1e30f}, {-1e30f, -1e30f}};
    float lrow[2][2] = {{0.f, 0.f}, {0.f, 0.f}};

    const __half* khb = g_Kh + (size_t)bh * SS * DHH;
    const __half* vhb = g_Vh + (size_t)bh * DHH * SS;

    const int nkt = qt * 2 + 2;

    // preload tile 0
    #pragma unroll
    for (int i = 0; i < 4; i++) {
        const int idx = i * 128 + tid;
        const int row = idx >> 3, c = idx & 7;
        cp16(smb + row * APITCH + c * 16,        khb + row * 64 + c * 8);
        cp16(smb + 9216 + row * APITCH + c * 16, vhb + (size_t)row * SS + c * 8);
    }
    CP_COMMIT();

    #pragma unroll 1
    for (int jt = 0; jt < nkt; jt++) {
        CP_WAIT0();
        __syncthreads();
        if (jt + 1 < nkt) {
            const uint32_t base = smb + ((jt + 1) & 1) * AST;
            const int j1 = (jt + 1) * 64;
            #pragma unroll
            for (int i = 0; i < 4; i++) {
                const int idx = i * 128 + tid;
                const int row = idx >> 3, c = idx & 7;
                cp16(base + row * APITCH + c * 16,        khb + (size_t)(j1 + row) * 64 + c * 8);
                cp16(base + 9216 + row * APITCH + c * 16, vhb + (size_t)row * SS + j1 + c * 8);
            }
        }
        CP_COMMIT();

        const uint32_t kb = smb + (jt & 1) * AST;
        const int j0 = jt * 64;

        // ---- S = Q K^T (already in log2 units via Q pre-scale) ----
        float s2[2][8][4];
        #pragma unroll
        for (int mt = 0; mt < 2; mt++)
            #pragma unroll
            for (int nt = 0; nt < 8; nt++)
                #pragma unroll
                for (int e = 0; e < 4; e++) s2[mt][nt][e] = 0.0f;

        #pragma unroll
        for (int kc = 0; kc < 4; kc++) {
            uint32_t b[4][4];
            #pragma unroll
            for (int bt = 0; bt < 4; bt++)
                ldm_x4(b[bt], kb + (bt * 16 + (lane & 15)) * APITCH
                             + (kc * 2 + (lane >> 4)) * 16);
            #pragma unroll
            for (int mt = 0; mt < 2; mt++)
                #pragma unroll
                for (int nt = 0; nt < 8; nt++)
                    mma16816(s2[mt][nt], qh[mt][kc], b[nt >> 1][nt & 1], b[nt >> 1][(nt & 1) + 2]);
        }

        // ---- mask + online softmax (exp2 space) ----
        const bool need_mask = (j0 + 63 > q0 + w * 32);
        #pragma unroll
        for (int mt = 0; mt < 2; mt++) {
            #pragma unroll
            for (int rs = 0; rs < 2; rs++) {
                const int row = q0 + w * 32 + mt * 16 + g + rs * 8;
                if (need_mask) {
                    #pragma unroll
                    for (int nt = 0; nt < 8; nt++)
                        #pragma unroll
                        for (int e = 0; e < 2; e++) {
                            const int key = j0 + nt * 8 + tg * 2 + e;
                            if (key > row) s2[mt][nt][rs * 2 + e] = -1e30f;
                        }
                }
                float mx = -1e30f;
                #pragma unroll
                for (int nt = 0; nt < 8; nt++)
                    mx = fmaxf(mx, fmaxf(s2[mt][nt][rs * 2], s2[mt][nt][rs * 2 + 1]));
                mx = fmaxf(mx, __shfl_xor_sync(0xffffffffu, mx, 1));
                mx = fmaxf(mx, __shfl_xor_sync(0xffffffffu, mx, 2));
                const float mn = fmaxf(mrow[mt][rs], mx);
                const float sc = exp2f(mrow[mt][rs] - mn);
                mrow[mt][rs] = mn;
                float ps = 0.0f;
                #pragma unroll
                for (int nt = 0; nt < 8; nt++) {
                    float p0 = exp2f(s2[mt][nt][rs * 2]     - mn);
                    float p1 = exp2f(s2[mt][nt][rs * 2 + 1] - mn);
                    s2[mt][nt][rs * 2] = p0; s2[mt][nt][rs * 2 + 1] = p1;
                    ps += p0 + p1;
                    o[mt][nt][rs * 2] *= sc; o[mt][nt][rs * 2 + 1] *= sc;
                }
                lrow[mt][rs] = lrow[mt][rs] * sc + ps;
            }
        }

        // ---- O += P V ----
        #pragma unroll
        for (int kc = 0; kc < 4; kc++) {
            uint32_t b[4][4];
            #pragma unroll
            for (int bt = 0; bt < 4; bt++)
                ldm_x4(b[bt], kb + 9216 + (bt * 16 + (lane & 15)) * APITCH
                             + (kc * 2 + (lane >> 4)) * 16);
            #pragma unroll
            for (int mt = 0; mt < 2; mt++) {
                uint32_t a[4];
                a[0] = packhf(s2[mt][2*kc][1],   s2[mt][2*kc][0]);
                a[1] = packhf(s2[mt][2*kc][3],   s2[mt][2*kc][2]);
                a[2] = packhf(s2[mt][2*kc+1][1], s2[mt][2*kc+1][0]);
                a[3] = packhf(s2[mt][2*kc+1][3], s2[mt][2*kc+1][2]);
                #pragma unroll
                for (int nt = 0; nt < 8; nt++)
                    mma16816(o[mt][nt], a, b[nt >> 1][nt & 1], b[nt >> 1][(nt & 1) + 2]);
            }
        }
    }

    // ---- finalize: normalize, write out[b, s, h*64+dh] ----
    const int b = bh >> 4, h = bh & 15;
    #pragma unroll
    for (int mt = 0; mt < 2; mt++) {
        float l0 = lrow[mt][0];
        l0 += __shfl_xor_sync(0xffffffffu, l0, 1);
        l0 += __shfl_xor_sync(0xffffffffu, l0, 2);
        float l1 = lrow[mt][1];
        l1 += __shfl_xor_sync(0xffffffffu, l1, 1);
        l1 += __shfl_xor_sync(0xffffffffu, l1, 2);
        const float i0 = 1.0f / l0, i1 = 1.0f / l1;
        const int row = q0 + w * 32 + mt * 16 + g;
        #pragma unroll
        for (int nt = 0; nt < 8; nt++) {
            const int col = h * 64 + nt * 8 + tg * 2;
            float2 v0 = make_float2(o[mt][nt][0] * i0, o[mt][nt][1] * i0);
            *(float2*)(out + ((size_t)(b * SS + row)) * DD + col) = v0;
            float2 v1 = make_float2(o[mt][nt][2] * i1, o[mt][nt][3] * i1);
            *(float2*)(out + ((size_t)(b * SS + row + 8)) * DD + col) = v1;
        }
    }
}

// ---------------------------------------------------------------------------
extern "C" void kernel_launch(void* const* d_in, const int* in_sizes, int n_in,
                              void* d_out, int out_size)
{
    const float* x    = (const float*)d_in[0];   // [B,S,D]
    const float* W    = (const float*)d_in[1];   // [D,3D]
    const float* bias = (const float*)d_in[2];   // [3D]
    float* out        = (float*)d_out;           // [B,S,D]

    cudaFuncSetAttribute(qkv_gemm_hmma, cudaFuncAttributeMaxDynamicSharedMemorySize, GEMM_SMEM);
    cudaFuncSetAttribute(attn_hmma,     cudaFuncAttributeMaxDynamicSharedMemorySize, ATT_SMEM);

    conv_x_kernel<<<(MTOT * KTOT) / (8 * 256), 256>>>(x);
    conv_w_kernel<<<dim3(NTOT / 32, KTOT / 32), 256>>>(W);

    dim3 gemm_grid(NTOT / 128, MTOT / 256);   // (24, 32)
    qkv_gemm_hmma<<<gemm_grid, 256, GEMM_SMEM>>>(bias);

    dim3 attn_grid(SS / 128, BB * HH);        // (16, 64)
    attn_hmma<<<attn_grid, 128, ATT_SMEM>>>(out);
}

// round 7
// speedup vs baseline: 1.0492x; 1.0492x over previous
#include <cuda_runtime.h>
#include <cuda_fp16.h>
#include <cstdint>

// Problem constants
#define BB 4
#define SS 2048
#define DD 1024
#define HH 16
#define DHH 64
#define MTOT (BB*SS)     // 8192
#define NTOT (3*DD)      // 3072
#define KTOT (DD)        // 1024

#define QKVN ((size_t)BB*HH*SS*DHH)

// Q pre-scale: 1/sqrt(64) * log2(e)  (softmax done in exp2 space)
#define QSCALE 0.1803368801111204f

// Scratch: fp16 single-precision-pass operands
__device__ __align__(16) __half g_A[(size_t)MTOT*KTOT];   // x   [M, K] K-major
__device__ __align__(16) __half g_B[(size_t)NTOT*KTOT];   // W^T [N, K] K-major
__device__ __align__(16) __half g_Qh[QKVN];               // [B,H,S,64] (pre-scaled)
__device__ __align__(16) __half g_Kh[QKVN];               // [B,H,S,64]
__device__ __align__(16) __half g_Vh[QKVN];               // [B,H,64,S] (transposed)

// ---------------------------------------------------------------------------
// Helpers (sm_103 baseline-safe: ldmatrix / mma.sync / cp.async only)
// ---------------------------------------------------------------------------
__device__ __forceinline__ uint32_t smem_u32(const void* p) {
    uint32_t a;
    asm("{ .reg .u64 t; cvta.to.shared.u64 t, %1; cvt.u32.u64 %0, t; }" : "=r"(a) : "l"(p));
    return a;
}
__device__ __forceinline__ void ldm_x4(uint32_t* r, uint32_t addr) {
    asm volatile("ldmatrix.sync.aligned.m8n8.x4.shared.b16 {%0,%1,%2,%3}, [%4];"
        : "=r"(r[0]), "=r"(r[1]), "=r"(r[2]), "=r"(r[3]) : "r"(addr));
}
__device__ __forceinline__ void mma16816(float* d, const uint32_t* a, uint32_t b0, uint32_t b1) {
    asm volatile("mma.sync.aligned.m16n8k16.row.col.f32.f16.f16.f32 "
        "{%0,%1,%2,%3}, {%4,%5,%6,%7}, {%8,%9}, {%0,%1,%2,%3};"
        : "+f"(d[0]), "+f"(d[1]), "+f"(d[2]), "+f"(d[3])
        : "r"(a[0]), "r"(a[1]), "r"(a[2]), "r"(a[3]), "r"(b0), "r"(b1));
}
__device__ __forceinline__ void cp16(uint32_t dst, const void* src) {
    asm volatile("cp.async.cg.shared.global [%0], [%1], 16;" :: "r"(dst), "l"(src));
}
#define CP_COMMIT() asm volatile("cp.async.commit_group;" ::: "memory")
#define CP_WAIT1()  asm volatile("cp.async.wait_group 1;" ::: "memory")
#define CP_WAIT0()  asm volatile("cp.async.wait_group 0;" ::: "memory")

__device__ __forceinline__ uint32_t packhf(float e1, float e0) {
    uint32_t r; asm("cvt.rn.f16x2.f32 %0, %1, %2;" : "=r"(r) : "f"(e1), "f"(e0)); return r;
}

// ---------------------------------------------------------------------------
// Conversion: x [M,K] fp32 -> g_A fp16 (8 elements per thread)
// ---------------------------------------------------------------------------
__global__ __launch_bounds__(256) void conv_x_kernel(const float* __restrict__ x)
{
    const int base = (blockIdx.x * 256 + threadIdx.x) * 8;
    float4 v0 = *(const float4*)(x + base);
    float4 v1 = *(const float4*)(x + base + 4);
    __half h[8];
    h[0] = __float2half(v0.x); h[1] = __float2half(v0.y);
    h[2] = __float2half(v0.z); h[3] = __float2half(v0.w);
    h[4] = __float2half(v1.x); h[5] = __float2half(v1.y);
    h[6] = __float2half(v1.z); h[7] = __float2half(v1.w);
    *(float4*)(g_A + base) = *(float4*)h;
}

// ---------------------------------------------------------------------------
// Conversion: W [K,N] fp32 -> g_B [N,K] fp16 (transpose, 16B stores)
// ---------------------------------------------------------------------------
__global__ __launch_bounds__(256) void conv_w_kernel(const float* __restrict__ W)
{
    __shared__ float T[32][33];
    const int n0 = blockIdx.x * 32;
    const int k0 = blockIdx.y * 32;
    const int tid = threadIdx.x;
    const int tx = tid & 31, ty = tid >> 5;

    #pragma unroll
    for (int i = 0; i < 4; i++)
        T[ty + i * 8][tx] = W[(size_t)(k0 + ty + i * 8) * NTOT + n0 + tx];
    __syncthreads();

    if (tid < 128) {
        const int nl = tid >> 2;          // 0..31
        const int kq = (tid & 3) * 8;     // 0,8,16,24
        __half h[8];
        #pragma unroll
        for (int i = 0; i < 8; i++) h[i] = __float2half(T[kq + i][nl]);
        *(float4*)(g_B + (size_t)(n0 + nl) * KTOT + k0 + kq) = *(float4*)h;
    }
}

// ---------------------------------------------------------------------------
// HMMA GEMM (R5 config): C[8192,3072] = A @ B^T. CTA 128x128, warp tile
// 64x32 (2x4 warps), BK=32, 3-stage cp.async, 2 CTAs/SM.
// Epilogue: +bias -> fp16 Q(xQSCALE)/K/V^T.
// ---------------------------------------------------------------------------
#define ROWB 80
#define STG_BYTES (128*ROWB*2)
#define GSTG 3
#define GEMM_SMEM (GSTG*STG_BYTES)  // 61440

__device__ __forceinline__ void gemm_load_stage(uint32_t smb, int s, int kc,
                                                int m0, int n0, int tid)
{
    const int row = tid >> 1;
    const int c0  = (tid & 1) * 2;
    const __half* asrc = g_A + (size_t)(m0 + row) * KTOT + kc + c0 * 8;
    uint32_t adst = smb + s * STG_BYTES + row * ROWB + c0 * 16;
    cp16(adst,      asrc);
    cp16(adst + 16, asrc + 8);
    const __half* bsrc = g_B + (size_t)(n0 + row) * KTOT + kc + c0 * 8;
    uint32_t bdst = smb + s * STG_BYTES + 128 * ROWB + row * ROWB + c0 * 16;
    cp16(bdst,      bsrc);
    cp16(bdst + 16, bsrc + 8);
}

__global__ __launch_bounds__(256, 2) void qkv_gemm_hmma(const float* __restrict__ bias)
{
    extern __shared__ __align__(16) char sm[];
    const uint32_t smb = smem_u32(sm);
    const int tid = threadIdx.x, lane = tid & 31, wid = tid >> 5;
    const int m0 = blockIdx.y * 128;
    const int n0 = blockIdx.x * 128;
    const int wm = wid & 1;
    const int wn = wid >> 1;

    float acc[4][4][4];
    #pragma unroll
    for (int i = 0; i < 4; i++)
        #pragma unroll
        for (int j = 0; j < 4; j++)
            #pragma unroll
            for (int r = 0; r < 4; r++) acc[i][j][r] = 0.0f;

    gemm_load_stage(smb, 0, 0,  m0, n0, tid);
    CP_COMMIT();
    gemm_load_stage(smb, 1, 32, m0, n0, tid);
    CP_COMMIT();

    const int NIT = KTOT / 32;   // 32
    for (int it = 0; it < NIT; it++) {
        CP_WAIT1();
        __syncthreads();
        if (it + 2 < NIT)
            gemm_load_stage(smb, (it + 2) % GSTG, (it + 2) * 32, m0, n0, tid);
        CP_COMMIT();

        const uint32_t sb = smb + (it % GSTG) * STG_BYTES;
        #pragma unroll
        for (int ks = 0; ks < 2; ks++) {
            uint32_t a[4][4], b[2][4];
            #pragma unroll
            for (int mt = 0; mt < 4; mt++) {
                const int r = wm * 64 + mt * 16 + (lane & 15);
                ldm_x4(a[mt], sb + r * ROWB + (ks * 2 + (lane >> 4)) * 16);
            }
            #pragma unroll
            for (int bt = 0; bt < 2; bt++) {
                const int r = wn * 32 + bt * 16 + (lane & 15);
                ldm_x4(b[bt], sb + 128 * ROWB + r * ROWB + (ks * 2 + (lane >> 4)) * 16);
            }
            #pragma unroll
            for (int mt = 0; mt < 4; mt++)
                #pragma unroll
                for (int nt = 0; nt < 4; nt++) {
                    const int bt = nt >> 1, sub = nt & 1;
                    mma16816(acc[mt][nt], a[mt], b[bt][sub], b[bt][sub + 2]);
                }
        }
    }

    // Epilogue: +bias, fp16, write Q (xQSCALE) / K (row-major) and V (transposed)
    #pragma unroll
    for (int mt = 0; mt < 4; mt++) {
        #pragma unroll
        for (int nt = 0; nt < 4; nt++) {
            const int m = m0 + wm * 64 + mt * 16 + (lane >> 2);
            const int n = n0 + wn * 32 + (nt >> 1) * 16 + (nt & 1) * 8 + 2 * (lane & 3);
            const float2 bb = *(const float2*)(bias + n);
            const int hh    = n / 192;
            const int which = (n >> 6) % 3;
            const int dh    = n & 63;
            const int bi = m >> 11, si = m & 2047;
            const int bh = bi * HH + hh;
            #pragma unroll
            for (int rr = 0; rr < 2; rr++) {
                const int s = si + rr * 8;
                float vx = acc[mt][nt][rr * 2 + 0] + bb.x;
                float vy = acc[mt][nt][rr * 2 + 1] + bb.y;
                if (which == 0) { vx *= QSCALE; vy *= QSCALE; }
                if (which == 2) {
                    const size_t vb = ((size_t)bh * DHH + dh) * SS + s;
                    g_Vh[vb]      = __float2half(vx);
                    g_Vh[vb + SS] = __float2half(vy);
                } else {
                    const size_t qb = ((size_t)bh * SS + s) * DHH + dh;
                    __half2 hv; hv.x = __float2half(vx); hv.y = __float2half(vy);
                    *(__half2*)(((which == 0) ? g_Qh : g_Kh) + qb) = hv;
                }
            }
        }
    }
}

// ---------------------------------------------------------------------------
// HMMA causal flash attention, fp16, exp2-space softmax.
// CTA: 128 q rows, 4 warps x 32 rows. K-tiles of 64 keys, double-buffered.
// Heavy-first scheduling: qt reversed so diagonal-heavy CTAs launch first.
// ---------------------------------------------------------------------------
#define APITCH 144
#define AST 18432   // stage bytes: Kh@0, Vh@9216 (64 rows x 144B)
#define ATT_SMEM (2*AST)  // 36864

__global__ __launch_bounds__(128) void attn_hmma(float* __restrict__ out)
{
    extern __shared__ __align__(16) char sm[];
    const uint32_t smb = smem_u32(sm);
    const int tid = threadIdx.x, lane = tid & 31, w = tid >> 5;
    const int bh = blockIdx.y;
    const int qt = (int)gridDim.x - 1 - (int)blockIdx.x;   // heavy blocks first
    const int q0 = qt * 128;
    const int tg = lane & 3, g = lane >> 2;

    // --- stage Q tile, then ldmatrix into regs ---
    {
        const __half* qhg = g_Qh + ((size_t)bh * SS + q0) * DHH;
        #pragma unroll
        for (int i = 0; i < 8; i++) {
            const int idx = i * 128 + tid;
            const int row = idx >> 3, c = idx & 7;
            *(float4*)(sm + row * APITCH + c * 16) = *(const float4*)(qhg + row * 64 + c * 8);
        }
    }
    __syncthreads();
    uint32_t qh[2][4][4];
    #pragma unroll
    for (int mt = 0; mt < 2; mt++)
        #pragma unroll
        for (int kc = 0; kc < 4; kc++)
            ldm_x4(qh[mt][kc], smb + (w * 32 + mt * 16 + (lane & 15)) * APITCH
                              + (kc * 2 + (lane >> 4)) * 16);
    __syncthreads();

    float o[2][8][4];
    #pragma unroll
    for (int mt = 0; mt < 2; mt++)
        #pragma unroll
        for (int nt = 0; nt < 8; nt++)
            #pragma unroll
            for (int e = 0; e < 4; e++) o[mt][nt][e] = 0.0f;
    float mrow[2][2] = {{-1e30f, -1e30f}, {-1e30f, -1e30f}};
    float lrow[2][2] = {{0.f, 0.f}, {0.f, 0.f}};

    const __half* khb = g_Kh + (size_t)bh * SS * DHH;
    const __half* vhb = g_Vh + (size_t)bh * DHH * SS;

    const int nkt = qt * 2 + 2;

    // preload tile 0
    #pragma unroll
    for (int i = 0; i < 4; i++) {
        const int idx = i * 128 + tid;
        const int row = idx >> 3, c = idx & 7;
        cp16(smb + row * APITCH + c * 16,        khb + row * 64 + c * 8);
        cp16(smb + 9216 + row * APITCH + c * 16, vhb + (size_t)row * SS + c * 8);
    }
    CP_COMMIT();

    #pragma unroll 1
    for (int jt = 0; jt < nkt; jt++) {
        CP_WAIT0();
        __syncthreads();
        if (jt + 1 < nkt) {
            const uint32_t base = smb + ((jt + 1) & 1) * AST;
            const int j1 = (jt + 1) * 64;
            #pragma unroll
            for (int i = 0; i < 4; i++) {
                const int idx = i * 128 + tid;
                const int row = idx >> 3, c = idx & 7;
                cp16(base + row * APITCH + c * 16,        khb + (size_t)(j1 + row) * 64 + c * 8);
                cp16(base + 9216 + row * APITCH + c * 16, vhb + (size_t)row * SS + j1 + c * 8);
            }
        }
        CP_COMMIT();

        const uint32_t kb = smb + (jt & 1) * AST;
        const int j0 = jt * 64;

        // ---- S = Q K^T (already in log2 units via Q pre-scale) ----
        float s2[2][8][4];
        #pragma unroll
        for (int mt = 0; mt < 2; mt++)
            #pragma unroll
            for (int nt = 0; nt < 8; nt++)
                #pragma unroll
                for (int e = 0; e < 4; e++) s2[mt][nt][e] = 0.0f;

        #pragma unroll
        for (int kc = 0; kc < 4; kc++) {
            uint32_t b[4][4];
            #pragma unroll
            for (int bt = 0; bt < 4; bt++)
                ldm_x4(b[bt], kb + (bt * 16 + (lane & 15)) * APITCH
                             + (kc * 2 + (lane >> 4)) * 16);
            #pragma unroll
            for (int mt = 0; mt < 2; mt++)
                #pragma unroll
                for (int nt = 0; nt < 8; nt++)
                    mma16816(s2[mt][nt], qh[mt][kc], b[nt >> 1][nt & 1], b[nt >> 1][(nt & 1) + 2]);
        }

        // ---- mask + online softmax (exp2 space) ----
        const bool need_mask = (j0 + 63 > q0 + w * 32);
        #pragma unroll
        for (int mt = 0; mt < 2; mt++) {
            #pragma unroll
            for (int rs = 0; rs < 2; rs++) {
                const int row = q0 + w * 32 + mt * 16 + g + rs * 8;
                if (need_mask) {
                    #pragma unroll
                    for (int nt = 0; nt < 8; nt++)
                        #pragma unroll
                        for (int e = 0; e < 2; e++) {
                            const int key = j0 + nt * 8 + tg * 2 + e;
                            if (key > row) s2[mt][nt][rs * 2 + e] = -1e30f;
                        }
                }
                float mx = -1e30f;
                #pragma unroll
                for (int nt = 0; nt < 8; nt++)
                    mx = fmaxf(mx, fmaxf(s2[mt][nt][rs * 2], s2[mt][nt][rs * 2 + 1]));
                mx = fmaxf(mx, __shfl_xor_sync(0xffffffffu, mx, 1));
                mx = fmaxf(mx, __shfl_xor_sync(0xffffffffu, mx, 2));
                const float mn = fmaxf(mrow[mt][rs], mx);
                const float sc = exp2f(mrow[mt][rs] - mn);
                mrow[mt][rs] = mn;
                float ps = 0.0f;
                #pragma unroll
                for (int nt = 0; nt < 8; nt++) {
                    float p0 = exp2f(s2[mt][nt][rs * 2]     - mn);
                    float p1 = exp2f(s2[mt][nt][rs * 2 + 1] - mn);
                    s2[mt][nt][rs * 2] = p0; s2[mt][nt][rs * 2 + 1] = p1;
                    ps += p0 + p1;
                    o[mt][nt][rs * 2] *= sc; o[mt][nt][rs * 2 + 1] *= sc;
                }
                lrow[mt][rs] = lrow[mt][rs] * sc + ps;
            }
        }

        // ---- O += P V ----
        #pragma unroll
        for (int kc = 0; kc < 4; kc++) {
            uint32_t b[4][4];
            #pragma unroll
            for (int bt = 0; bt < 4; bt++)
                ldm_x4(b[bt], kb + 9216 + (bt * 16 + (lane & 15)) * APITCH
                             + (kc * 2 + (lane >> 4)) * 16);
            #pragma unroll
            for (int mt = 0; mt < 2; mt++) {
                uint32_t a[4];
                a[0] = packhf(s2[mt][2*kc][1],   s2[mt][2*kc][0]);
                a[1] = packhf(s2[mt][2*kc][3],   s2[mt][2*kc][2]);
                a[2] = packhf(s2[mt][2*kc+1][1], s2[mt][2*kc+1][0]);
                a[3] = packhf(s2[mt][2*kc+1][3], s2[mt][2*kc+1][2]);
                #pragma unroll
                for (int nt = 0; nt < 8; nt++)
                    mma16816(o[mt][nt], a, b[nt >> 1][nt & 1], b[nt >> 1][(nt & 1) + 2]);
            }
        }
    }

    // ---- finalize: normalize, write out[b, s, h*64+dh] ----
    const int b = bh >> 4, h = bh & 15;
    #pragma unroll
    for (int mt = 0; mt < 2; mt++) {
        float l0 = lrow[mt][0];
        l0 += __shfl_xor_sync(0xffffffffu, l0, 1);
        l0 += __shfl_xor_sync(0xffffffffu, l0, 2);
        float l1 = lrow[mt][1];
        l1 += __shfl_xor_sync(0xffffffffu, l1, 1);
        l1 += __shfl_xor_sync(0xffffffffu, l1, 2);
        const float i0 = 1.0f / l0, i1 = 1.0f / l1;
        const int row = q0 + w * 32 + mt * 16 + g;
        #pragma unroll
        for (int nt = 0; nt < 8; nt++) {
            const int col = h * 64 + nt * 8 + tg * 2;
            float2 v0 = make_float2(o[mt][nt][0] * i0, o[mt][nt][1] * i0);
            *(float2*)(out + ((size_t)(b * SS + row)) * DD + col) = v0;
            float2 v1 = make_float2(o[mt][nt][2] * i1, o[mt][nt][3] * i1);
            *(float2*)(out + ((size_t)(b * SS + row + 8)) * DD + col) = v1;
        }
    }
}

// ---------------------------------------------------------------------------
extern "C" void kernel_launch(void* const* d_in, const int* in_sizes, int n_in,
                              void* d_out, int out_size)
{
    const float* x    = (const float*)d_in[0];   // [B,S,D]
    const float* W    = (const float*)d_in[1];   // [D,3D]
    const float* bias = (const float*)d_in[2];   // [3D]
    float* out        = (float*)d_out;           // [B,S,D]

    cudaFuncSetAttribute(qkv_gemm_hmma, cudaFuncAttributeMaxDynamicSharedMemorySize, GEMM_SMEM);
    cudaFuncSetAttribute(attn_hmma,     cudaFuncAttributeMaxDynamicSharedMemorySize, ATT_SMEM);

    conv_x_kernel<<<(MTOT * KTOT) / (8 * 256), 256>>>(x);
    conv_w_kernel<<<dim3(NTOT / 32, KTOT / 32), 256>>>(W);

    dim3 gemm_grid(NTOT / 128, MTOT / 128);   // (24, 64)
    qkv_gemm_hmma<<<gemm_grid, 256, GEMM_SMEM>>>(bias);

    dim3 attn_grid(SS / 128, BB * HH);        // (16, 64)
    attn_hmma<<<attn_grid, 128, ATT_SMEM>>>(out);
}

// round 8
// speedup vs baseline: 1.1290x; 1.0760x over previous
#include <cuda_runtime.h>
#include <cuda_fp16.h>
#include <cstdint>

// Problem constants
#define BB 4
#define SS 2048
#define DD 1024
#define HH 16
#define DHH 64
#define MTOT (BB*SS)     // 8192
#define NTOT (3*DD)      // 3072
#define KTOT (DD)        // 1024

#define QKVN ((size_t)BB*HH*SS*DHH)

// Q pre-scale: 1/sqrt(64) * log2(e)  (softmax done in exp2 space)
#define QSCALE 0.1803368801111204f

// Scratch: fp16 single-precision-pass operands
__device__ __align__(16) __half g_A[(size_t)MTOT*KTOT];   // x   [M, K] K-major
__device__ __align__(16) __half g_B[(size_t)NTOT*KTOT];   // W^T [N, K] K-major
__device__ __align__(16) __half g_Qh[QKVN];               // [B,H,S,64] (pre-scaled)
__device__ __align__(16) __half g_Kh[QKVN];               // [B,H,S,64]
__device__ __align__(16) __half g_Vh[QKVN];               // [B,H,64,S] (transposed)

// ---------------------------------------------------------------------------
// Helpers (sm_103 baseline-safe: ldmatrix / mma.sync / cp.async only)
// ---------------------------------------------------------------------------
__device__ __forceinline__ uint32_t smem_u32(const void* p) {
    uint32_t a;
    asm("{ .reg .u64 t; cvta.to.shared.u64 t, %1; cvt.u32.u64 %0, t; }" : "=r"(a) : "l"(p));
    return a;
}
__device__ __forceinline__ void ldm_x4(uint32_t* r, uint32_t addr) {
    asm volatile("ldmatrix.sync.aligned.m8n8.x4.shared.b16 {%0,%1,%2,%3}, [%4];"
        : "=r"(r[0]), "=r"(r[1]), "=r"(r[2]), "=r"(r[3]) : "r"(addr));
}
__device__ __forceinline__ void mma16816(float* d, const uint32_t* a, uint32_t b0, uint32_t b1) {
    asm volatile("mma.sync.aligned.m16n8k16.row.col.f32.f16.f16.f32 "
        "{%0,%1,%2,%3}, {%4,%5,%6,%7}, {%8,%9}, {%0,%1,%2,%3};"
        : "+f"(d[0]), "+f"(d[1]), "+f"(d[2]), "+f"(d[3])
        : "r"(a[0]), "r"(a[1]), "r"(a[2]), "r"(a[3]), "r"(b0), "r"(b1));
}
__device__ __forceinline__ void cp16(uint32_t dst, const void* src) {
    asm volatile("cp.async.cg.shared.global [%0], [%1], 16;" :: "r"(dst), "l"(src));
}
#define CP_COMMIT() asm volatile("cp.async.commit_group;" ::: "memory")
#define CP_WAIT2()  asm volatile("cp.async.wait_group 2;" ::: "memory")
#define CP_WAIT0()  asm volatile("cp.async.wait_group 0;" ::: "memory")

__device__ __forceinline__ uint32_t packhf(float e1, float e0) {
    uint32_t r; asm("cvt.rn.f16x2.f32 %0, %1, %2;" : "=r"(r) : "f"(e1), "f"(e0)); return r;
}
__device__ __forceinline__ float ex2f(float x) {
    float y; asm("ex2.approx.ftz.f32 %0, %1;" : "=f"(y) : "f"(x)); return y;
}

// ---------------------------------------------------------------------------
// Conversion: x [M,K] fp32 -> g_A fp16 (8 elements per thread)
// ---------------------------------------------------------------------------
__global__ __launch_bounds__(256) void conv_x_kernel(const float* __restrict__ x)
{
    const int base = (blockIdx.x * 256 + threadIdx.x) * 8;
    float4 v0 = *(const float4*)(x + base);
    float4 v1 = *(const float4*)(x + base + 4);
    __half h[8];
    h[0] = __float2half(v0.x); h[1] = __float2half(v0.y);
    h[2] = __float2half(v0.z); h[3] = __float2half(v0.w);
    h[4] = __float2half(v1.x); h[5] = __float2half(v1.y);
    h[6] = __float2half(v1.z); h[7] = __float2half(v1.w);
    *(float4*)(g_A + base) = *(float4*)h;
}

// ---------------------------------------------------------------------------
// Conversion: W [K,N] fp32 -> g_B [N,K] fp16 (transpose, 16B stores)
// ---------------------------------------------------------------------------
__global__ __launch_bounds__(256) void conv_w_kernel(const float* __restrict__ W)
{
    __shared__ float T[32][33];
    const int n0 = blockIdx.x * 32;
    const int k0 = blockIdx.y * 32;
    const int tid = threadIdx.x;
    const int tx = tid & 31, ty = tid >> 5;

    #pragma unroll
    for (int i = 0; i < 4; i++)
        T[ty + i * 8][tx] = W[(size_t)(k0 + ty + i * 8) * NTOT + n0 + tx];
    __syncthreads();

    if (tid < 128) {
        const int nl = tid >> 2;          // 0..31
        const int kq = (tid & 3) * 8;     // 0,8,16,24
        __half h[8];
        #pragma unroll
        for (int i = 0; i < 8; i++) h[i] = __float2half(T[kq + i][nl]);
        *(float4*)(g_B + (size_t)(n0 + nl) * KTOT + k0 + kq) = *(float4*)h;
    }
}

// ---------------------------------------------------------------------------
// HMMA GEMM: C[8192,3072] = A @ B^T. CTA 128x128, warp tile 64x32 (2x4 warps),
// BK=32, 4-stage cp.async, 2 CTAs/SM.
// Epilogue: smem-restaged coalesced stores -> fp16 Q(xQSCALE)/K/V^T.
// ---------------------------------------------------------------------------
#define ROWB 80
#define STG_BYTES (128*ROWB*2)       // 20480
#define GSTG 4
#define GEMM_SMEM (GSTG*STG_BYTES)   // 81920
#define EPW 5120                     // per-warp epilogue staging region

__device__ __forceinline__ void gemm_load_stage(uint32_t smb, int s, int kc,
                                                int m0, int n0, int tid)
{
    const int row = tid >> 1;
    const int c0  = (tid & 1) * 2;
    const __half* asrc = g_A + (size_t)(m0 + row) * KTOT + kc + c0 * 8;
    uint32_t adst = smb + s * STG_BYTES + row * ROWB + c0 * 16;
    cp16(adst,      asrc);
    cp16(adst + 16, asrc + 8);
    const __half* bsrc = g_B + (size_t)(n0 + row) * KTOT + kc + c0 * 8;
    uint32_t bdst = smb + s * STG_BYTES + 128 * ROWB + row * ROWB + c0 * 16;
    cp16(bdst,      bsrc);
    cp16(bdst + 16, bsrc + 8);
}

__global__ __launch_bounds__(256, 2) void qkv_gemm_hmma(const float* __restrict__ bias)
{
    extern __shared__ __align__(16) char sm[];
    const uint32_t smb = smem_u32(sm);
    const int tid = threadIdx.x, lane = tid & 31, wid = tid >> 5;
    const int m0 = blockIdx.y * 128;
    const int n0 = blockIdx.x * 128;
    const int wm = wid & 1;
    const int wn = wid >> 1;

    float acc[4][4][4];
    #pragma unroll
    for (int i = 0; i < 4; i++)
        #pragma unroll
        for (int j = 0; j < 4; j++)
            #pragma unroll
            for (int r = 0; r < 4; r++) acc[i][j][r] = 0.0f;

    gemm_load_stage(smb, 0, 0,  m0, n0, tid);
    CP_COMMIT();
    gemm_load_stage(smb, 1, 32, m0, n0, tid);
    CP_COMMIT();
    gemm_load_stage(smb, 2, 64, m0, n0, tid);
    CP_COMMIT();

    const int NIT = KTOT / 32;   // 32
    for (int it = 0; it < NIT; it++) {
        CP_WAIT2();
        __syncthreads();
        if (it + 3 < NIT)
            gemm_load_stage(smb, (it + 3) & 3, (it + 3) * 32, m0, n0, tid);
        CP_COMMIT();

        const uint32_t sb = smb + (it & 3) * STG_BYTES;
        #pragma unroll
        for (int ks = 0; ks < 2; ks++) {
            uint32_t a[4][4], b[2][4];
            #pragma unroll
            for (int mt = 0; mt < 4; mt++) {
                const int r = wm * 64 + mt * 16 + (lane & 15);
                ldm_x4(a[mt], sb + r * ROWB + (ks * 2 + (lane >> 4)) * 16);
            }
            #pragma unroll
            for (int bt = 0; bt < 2; bt++) {
                const int r = wn * 32 + bt * 16 + (lane & 15);
                ldm_x4(b[bt], sb + 128 * ROWB + r * ROWB + (ks * 2 + (lane >> 4)) * 16);
            }
            #pragma unroll
            for (int mt = 0; mt < 4; mt++)
                #pragma unroll
                for (int nt = 0; nt < 4; nt++) {
                    const int bt = nt >> 1, sub = nt & 1;
                    mma16816(acc[mt][nt], a[mt], b[bt][sub], b[bt][sub + 2]);
                }
        }
    }

    // ---- Epilogue: smem restage per warp, then coalesced global stores ----
    __syncthreads();   // all warps done reading stage smem

    // This warp's 64x32 patch is a single (head, q/k/v) segment (64 | n-base).
    const int seg   = (n0 + wn * 32) >> 6;   // 64-col segment id
    const int hh    = seg / 3;
    const int which = seg % 3;
    const int dh0   = (wn & 1) * 32;
    const int bi    = m0 >> 11;
    const int si0   = (m0 & 2047) + wm * 64;
    const int bh    = bi * HH + hh;
    char* ep = sm + wid * EPW;
    const float scl = (which == 0) ? QSCALE : 1.0f;

    if (which != 2) {
        // stage [s 64][dh 32], pitch 72B
        #pragma unroll
        for (int nt = 0; nt < 4; nt++) {
            const int c = (nt >> 1) * 16 + (nt & 1) * 8 + 2 * (lane & 3);
            const float2 bb = *(const float2*)(bias + n0 + wn * 32 + c);
            #pragma unroll
            for (int mt = 0; mt < 4; mt++)
                #pragma unroll
                for (int rr = 0; rr < 2; rr++) {
                    const int r = mt * 16 + (lane >> 2) + rr * 8;
                    const float vx = (acc[mt][nt][rr * 2 + 0] + bb.x) * scl;
                    const float vy = (acc[mt][nt][rr * 2 + 1] + bb.y) * scl;
                    *(uint32_t*)(ep + r * 72 + c * 2) = packhf(vy, vx);
                }
        }
        __syncwarp();
        __half* dstb = ((which == 0) ? g_Qh : g_Kh)
                     + ((size_t)bh * SS + si0) * DHH + dh0;
        #pragma unroll
        for (int p = 0; p < 16; p++) {
            const int slot = p * 32 + lane;
            const int r = slot >> 3, ch = slot & 7;
            float2 v = *(float2*)(ep + r * 72 + ch * 8);
            *(float2*)(dstb + (size_t)r * DHH + ch * 4) = v;
        }
    } else {
        // stage transposed [dh 32][s 64], pitch 136B
        #pragma unroll
        for (int nt = 0; nt < 4; nt++) {
            const int c = (nt >> 1) * 16 + (nt & 1) * 8 + 2 * (lane & 3);
            const float2 bb = *(const float2*)(bias + n0 + wn * 32 + c);
            #pragma unroll
            for (int mt = 0; mt < 4; mt++)
                #pragma unroll
                for (int rr = 0; rr < 2; rr++) {
                    const int r = mt * 16 + (lane >> 2) + rr * 8;
                    *(__half*)(ep + c * 136 + r * 2)       = __float2half(acc[mt][nt][rr*2+0] + bb.x);
                    *(__half*)(ep + (c + 1) * 136 + r * 2) = __float2half(acc[mt][nt][rr*2+1] + bb.y);
                }
        }
        __syncwarp();
        __half* dstb = g_Vh + ((size_t)bh * DHH + dh0) * SS + si0;
        #pragma unroll
        for (int p = 0; p < 16; p++) {
            const int slot = p * 32 + lane;
            const int d = slot >> 4, ch = slot & 15;
            float2 v = *(float2*)(ep + d * 136 + ch * 8);
            *(float2*)(dstb + (size_t)d * SS + ch * 4) = v;
        }
    }
}

// ---------------------------------------------------------------------------
// HMMA causal flash attention, fp16, exp2-space softmax (ex2.approx).
// CTA: 128 q rows, 4 warps x 32 rows. K-tiles of 64 keys, double-buffered.
// ---------------------------------------------------------------------------
#define APITCH 144
#define AST 18432   // stage bytes: Kh@0, Vh@9216 (64 rows x 144B)
#define ATT_SMEM (2*AST)  // 36864

__global__ __launch_bounds__(128) void attn_hmma(float* __restrict__ out)
{
    extern __shared__ __align__(16) char sm[];
    const uint32_t smb = smem_u32(sm);
    const int tid = threadIdx.x, lane = tid & 31, w = tid >> 5;
    const int bh = blockIdx.y, qt = blockIdx.x;
    const int q0 = qt * 128;
    const int tg = lane & 3, g = lane >> 2;

    // --- stage Q tile, then ldmatrix into regs ---
    {
        const __half* qhg = g_Qh + ((size_t)bh * SS + q0) * DHH;
        #pragma unroll
        for (int i = 0; i < 8; i++) {
            const int idx = i * 128 + tid;
            const int row = idx >> 3, c = idx & 7;
            *(float4*)(sm + row * APITCH + c * 16) = *(const float4*)(qhg + row * 64 + c * 8);
        }
    }
    __syncthreads();
    uint32_t qh[2][4][4];
    #pragma unroll
    for (int mt = 0; mt < 2; mt++)
        #pragma unroll
        for (int kc = 0; kc < 4; kc++)
            ldm_x4(qh[mt][kc], smb + (w * 32 + mt * 16 + (lane & 15)) * APITCH
                              + (kc * 2 + (lane >> 4)) * 16);
    __syncthreads();

    float o[2][8][4];
    #pragma unroll
    for (int mt = 0; mt < 2; mt++)
        #pragma unroll
        for (int nt = 0; nt < 8; nt++)
            #pragma unroll
            for (int e = 0; e < 4; e++) o[mt][nt][e] = 0.0f;
    float mrow[2][2] = {{-1e30f, -1e30f}, {-1e30f, -1e30f}};
    float lrow[2][2] = {{0.f, 0.f}, {0.f, 0.f}};

    const __half* khb = g_Kh + (size_t)bh * SS * DHH;
    const __half* vhb = g_Vh + (size_t)bh * DHH * SS;

    const int nkt = qt * 2 + 2;

    // preload tile 0
    #pragma unroll
    for (int i = 0; i < 4; i++) {
        const int idx = i * 128 + tid;
        const int row = idx >> 3, c = idx & 7;
        cp16(smb + row * APITCH + c * 16,        khb + row * 64 + c * 8);
        cp16(smb + 9216 + row * APITCH + c * 16, vhb + (size_t)row * SS + c * 8);
    }
    CP_COMMIT();

    #pragma unroll 1
    for (int jt = 0; jt < nkt; jt++) {
        CP_WAIT0();
        __syncthreads();
        if (jt + 1 < nkt) {
            const uint32_t base = smb + ((jt + 1) & 1) * AST;
            const int j1 = (jt + 1) * 64;
            #pragma unroll
            for (int i = 0; i < 4; i++) {
                const int idx = i * 128 + tid;
                const int row = idx >> 3, c = idx & 7;
                cp16(base + row * APITCH + c * 16,        khb + (size_t)(j1 + row) * 64 + c * 8);
                cp16(base + 9216 + row * APITCH + c * 16, vhb + (size_t)row * SS + j1 + c * 8);
            }
        }
        CP_COMMIT();

        const uint32_t kb = smb + (jt & 1) * AST;
        const int j0 = jt * 64;

        // ---- S = Q K^T (already in log2 units via Q pre-scale) ----
        float s2[2][8][4];
        #pragma unroll
        for (int mt = 0; mt < 2; mt++)
            #pragma unroll
            for (int nt = 0; nt < 8; nt++)
                #pragma unroll
                for (int e = 0; e < 4; e++) s2[mt][nt][e] = 0.0f;

        #pragma unroll
        for (int kc = 0; kc < 4; kc++) {
            uint32_t b[4][4];
            #pragma unroll
            for (int bt = 0; bt < 4; bt++)
                ldm_x4(b[bt], kb + (bt * 16 + (lane & 15)) * APITCH
                             + (kc * 2 + (lane >> 4)) * 16);
            #pragma unroll
            for (int mt = 0; mt < 2; mt++)
                #pragma unroll
                for (int nt = 0; nt < 8; nt++)
                    mma16816(s2[mt][nt], qh[mt][kc], b[nt >> 1][nt & 1], b[nt >> 1][(nt & 1) + 2]);
        }

        // ---- mask + online softmax (exp2 space) ----
        const bool need_mask = (j0 + 63 > q0 + w * 32);
        #pragma unroll
        for (int mt = 0; mt < 2; mt++) {
            #pragma unroll
            for (int rs = 0; rs < 2; rs++) {
                const int row = q0 + w * 32 + mt * 16 + g + rs * 8;
                if (need_mask) {
                    #pragma unroll
                    for (int nt = 0; nt < 8; nt++)
                        #pragma unroll
                        for (int e = 0; e < 2; e++) {
                            const int key = j0 + nt * 8 + tg * 2 + e;
                            if (key > row) s2[mt][nt][rs * 2 + e] = -1e30f;
                        }
                }
                float mx = -1e30f;
                #pragma unroll
                for (int nt = 0; nt < 8; nt++)
                    mx = fmaxf(mx, fmaxf(s2[mt][nt][rs * 2], s2[mt][nt][rs * 2 + 1]));
                mx = fmaxf(mx, __shfl_xor_sync(0xffffffffu, mx, 1));
                mx = fmaxf(mx, __shfl_xor_sync(0xffffffffu, mx, 2));
                const float mn = fmaxf(mrow[mt][rs], mx);
                const float sc = ex2f(mrow[mt][rs] - mn);
                mrow[mt][rs] = mn;
                float ps = 0.0f;
                #pragma unroll
                for (int nt = 0; nt < 8; nt++) {
                    float p0 = ex2f(s2[mt][nt][rs * 2]     - mn);
                    float p1 = ex2f(s2[mt][nt][rs * 2 + 1] - mn);
                    s2[mt][nt][rs * 2] = p0; s2[mt][nt][rs * 2 + 1] = p1;
                    ps += p0 + p1;
                    o[mt][nt][rs * 2] *= sc; o[mt][nt][rs * 2 + 1] *= sc;
                }
                lrow[mt][rs] = lrow[mt][rs] * sc + ps;
            }
        }

        // ---- O += P V ----
        #pragma unroll
        for (int kc = 0; kc < 4; kc++) {
            uint32_t b[4][4];
            #pragma unroll
            for (int bt = 0; bt < 4; bt++)
                ldm_x4(b[bt], kb + 9216 + (bt * 16 + (lane & 15)) * APITCH
                             + (kc * 2 + (lane >> 4)) * 16);
            #pragma unroll
            for (int mt = 0; mt < 2; mt++) {
                uint32_t a[4];
                a[0] = packhf(s2[mt][2*kc][1],   s2[mt][2*kc][0]);
                a[1] = packhf(s2[mt][2*kc][3],   s2[mt][2*kc][2]);
                a[2] = packhf(s2[mt][2*kc+1][1], s2[mt][2*kc+1][0]);
                a[3] = packhf(s2[mt][2*kc+1][3], s2[mt][2*kc+1][2]);
                #pragma unroll
                for (int nt = 0; nt < 8; nt++)
                    mma16816(o[mt][nt], a, b[nt >> 1][nt & 1], b[nt >> 1][(nt & 1) + 2]);
            }
        }
    }

    // ---- finalize: normalize, write out[b, s, h*64+dh] ----
    const int b = bh >> 4, h = bh & 15;
    #pragma unroll
    for (int mt = 0; mt < 2; mt++) {
        float l0 = lrow[mt][0];
        l0 += __shfl_xor_sync(0xffffffffu, l0, 1);
        l0 += __shfl_xor_sync(0xffffffffu, l0, 2);
        float l1 = lrow[mt][1];
        l1 += __shfl_xor_sync(0xffffffffu, l1, 1);
        l1 += __shfl_xor_sync(0xffffffffu, l1, 2);
        const float i0 = 1.0f / l0, i1 = 1.0f / l1;
        const int row = q0 + w * 32 + mt * 16 + g;
        #pragma unroll
        for (int nt = 0; nt < 8; nt++) {
            const int col = h * 64 + nt * 8 + tg * 2;
            float2 v0 = make_float2(o[mt][nt][0] * i0, o[mt][nt][1] * i0);
            *(float2*)(out + ((size_t)(b * SS + row)) * DD + col) = v0;
            float2 v1 = make_float2(o[mt][nt][2] * i1, o[mt][nt][3] * i1);
            *(float2*)(out + ((size_t)(b * SS + row + 8)) * DD + col) = v1;
        }
    }
}

// ---------------------------------------------------------------------------
extern "C" void kernel_launch(void* const* d_in, const int* in_sizes, int n_in,
                              void* d_out, int out_size)
{
    const float* x    = (const float*)d_in[0];   // [B,S,D]
    const float* W    = (const float*)d_in[1];   // [D,3D]
    const float* bias = (const float*)d_in[2];   // [3D]
    float* out        = (float*)d_out;           // [B,S,D]

    cudaFuncSetAttribute(qkv_gemm_hmma, cudaFuncAttributeMaxDynamicSharedMemorySize, GEMM_SMEM);
    cudaFuncSetAttribute(attn_hmma,     cudaFuncAttributeMaxDynamicSharedMemorySize, ATT_SMEM);

    conv_x_kernel<<<(MTOT * KTOT) / (8 * 256), 256>>>(x);
    conv_w_kernel<<<dim3(NTOT / 32, KTOT / 32), 256>>>(W);

    dim3 gemm_grid(NTOT / 128, MTOT / 128);   // (24, 64)
    qkv_gemm_hmma<<<gemm_grid, 256, GEMM_SMEM>>>(bias);

    dim3 attn_grid(SS / 128, BB * HH);        // (16, 64)
    attn_hmma<<<attn_grid, 128, ATT_SMEM>>>(out);
}

// round 9
// speedup vs baseline: 1.2374x; 1.0960x over previous
#include <cuda_runtime.h>
#include <cuda_fp16.h>
#include <cstdint>

// Problem constants
#define BB 4
#define SS 2048
#define DD 1024
#define HH 16
#define DHH 64
#define MTOT (BB*SS)     // 8192
#define NTOT (3*DD)      // 3072
#define KTOT (DD)        // 1024

#define QKVN ((size_t)BB*HH*SS*DHH)

// Q pre-scale: 1/sqrt(64) * log2(e)  (softmax done in exp2 space)
#define QSCALE 0.1803368801111204f

// Scratch: fp16 single-precision-pass operands
__device__ __align__(16) __half g_A[(size_t)MTOT*KTOT];   // x   [M, K] K-major
__device__ __align__(16) __half g_B[(size_t)NTOT*KTOT];   // W^T [N, K] K-major
__device__ __align__(16) __half g_Qh[QKVN];               // [B,H,S,64] (pre-scaled)
__device__ __align__(16) __half g_Kh[QKVN];               // [B,H,S,64]
__device__ __align__(16) __half g_Vh[QKVN];               // [B,H,64,S] (transposed)

// ---------------------------------------------------------------------------
// Helpers (sm_103 baseline-safe: ldmatrix / mma.sync / cp.async only)
// ---------------------------------------------------------------------------
__device__ __forceinline__ uint32_t smem_u32(const void* p) {
    uint32_t a;
    asm("{ .reg .u64 t; cvta.to.shared.u64 t, %1; cvt.u32.u64 %0, t; }" : "=r"(a) : "l"(p));
    return a;
}
__device__ __forceinline__ void ldm_x4(uint32_t* r, uint32_t addr) {
    asm volatile("ldmatrix.sync.aligned.m8n8.x4.shared.b16 {%0,%1,%2,%3}, [%4];"
        : "=r"(r[0]), "=r"(r[1]), "=r"(r[2]), "=r"(r[3]) : "r"(addr));
}
__device__ __forceinline__ void mma16816(float* d, const uint32_t* a, uint32_t b0, uint32_t b1) {
    asm volatile("mma.sync.aligned.m16n8k16.row.col.f32.f16.f16.f32 "
        "{%0,%1,%2,%3}, {%4,%5,%6,%7}, {%8,%9}, {%0,%1,%2,%3};"
        : "+f"(d[0]), "+f"(d[1]), "+f"(d[2]), "+f"(d[3])
        : "r"(a[0]), "r"(a[1]), "r"(a[2]), "r"(a[3]), "r"(b0), "r"(b1));
}
__device__ __forceinline__ void cp16(uint32_t dst, const void* src) {
    asm volatile("cp.async.cg.shared.global [%0], [%1], 16;" :: "r"(dst), "l"(src));
}
#define CP_COMMIT() asm volatile("cp.async.commit_group;" ::: "memory")
#define CP_WAIT1()  asm volatile("cp.async.wait_group 1;" ::: "memory")
#define CP_WAIT0()  asm volatile("cp.async.wait_group 0;" ::: "memory")

__device__ __forceinline__ uint32_t packhf(float e1, float e0) {
    uint32_t r; asm("cvt.rn.f16x2.f32 %0, %1, %2;" : "=r"(r) : "f"(e1), "f"(e0)); return r;
}
__device__ __forceinline__ float ex2f(float x) {
    float y; asm("ex2.approx.ftz.f32 %0, %1;" : "=f"(y) : "f"(x)); return y;
}

// ---------------------------------------------------------------------------
// Fused conversion kernel.
//   blocks [0, 4096):    x [M,K] fp32 -> g_A fp16 (8 elems/thread)
//   blocks [4096, 7168): W [K,N] fp32 -> g_B [N,K] fp16 (32x32 transpose tiles)
// ---------------------------------------------------------------------------
__global__ __launch_bounds__(256) void conv_fused(const float* __restrict__ x,
                                                  const float* __restrict__ W)
{
    if (blockIdx.x < 4096) {
        const int base = (blockIdx.x * 256 + threadIdx.x) * 8;
        float4 v0 = *(const float4*)(x + base);
        float4 v1 = *(const float4*)(x + base + 4);
        __half h[8];
        h[0] = __float2half(v0.x); h[1] = __float2half(v0.y);
        h[2] = __float2half(v0.z); h[3] = __float2half(v0.w);
        h[4] = __float2half(v1.x); h[5] = __float2half(v1.y);
        h[6] = __float2half(v1.z); h[7] = __float2half(v1.w);
        *(float4*)(g_A + base) = *(float4*)h;
    } else {
        __shared__ float T[32][33];
        const int blk = blockIdx.x - 4096;
        const int n0 = (blk % 96) * 32;
        const int k0 = (blk / 96) * 32;
        const int tid = threadIdx.x;
        const int tx = tid & 31, ty = tid >> 5;

        #pragma unroll
        for (int i = 0; i < 4; i++)
            T[ty + i * 8][tx] = W[(size_t)(k0 + ty + i * 8) * NTOT + n0 + tx];
        __syncthreads();

        if (tid < 128) {
            const int nl = tid >> 2;
            const int kq = (tid & 3) * 8;
            __half h[8];
            #pragma unroll
            for (int i = 0; i < 8; i++) h[i] = __float2half(T[kq + i][nl]);
            *(float4*)(g_B + (size_t)(n0 + nl) * KTOT + k0 + kq) = *(float4*)h;
        }
    }
}

// ---------------------------------------------------------------------------
// HMMA GEMM: C[8192,3072] = A @ B^T. CTA 128x128, warp tile 64x32 (2x4 warps),
// BK=64 (pitch 144B), 3-stage cp.async, 2 CTAs/SM.
// Epilogue: smem-restaged coalesced stores -> fp16 Q(xQSCALE)/K/V^T.
// ---------------------------------------------------------------------------
#define GROWB 144
#define GSTG_BYTES (256*GROWB)       // 36864 (A rows 0-127, B rows 128-255)
#define GB_OFF (128*GROWB)           // 18432
#define GSTG 3
#define GEMM_SMEM (GSTG*GSTG_BYTES)  // 110592
#define EPW 5120                     // per-warp epilogue staging region

__device__ __forceinline__ void gemm_load_stage(uint32_t smb, int s, int kc,
                                                int m0, int n0, int tid)
{
    const uint32_t base = smb + s * GSTG_BYTES;
    #pragma unroll
    for (int i = 0; i < 8; i++) {
        const int idx = i * 256 + tid;      // 0..2047
        const int row = idx >> 3, c = idx & 7;
        const __half* src = (row < 128)
            ? g_A + (size_t)(m0 + row) * KTOT + kc + c * 8
            : g_B + (size_t)(n0 + row - 128) * KTOT + kc + c * 8;
        cp16(base + row * GROWB + c * 16, src);
    }
}

__global__ __launch_bounds__(256, 2) void qkv_gemm_hmma(const float* __restrict__ bias)
{
    extern __shared__ __align__(16) char sm[];
    const uint32_t smb = smem_u32(sm);
    const int tid = threadIdx.x, lane = tid & 31, wid = tid >> 5;
    const int m0 = blockIdx.y * 128;
    const int n0 = blockIdx.x * 128;
    const int wm = wid & 1;
    const int wn = wid >> 1;

    float acc[4][4][4];
    #pragma unroll
    for (int i = 0; i < 4; i++)
        #pragma unroll
        for (int j = 0; j < 4; j++)
            #pragma unroll
            for (int r = 0; r < 4; r++) acc[i][j][r] = 0.0f;

    gemm_load_stage(smb, 0, 0,  m0, n0, tid);
    CP_COMMIT();
    gemm_load_stage(smb, 1, 64, m0, n0, tid);
    CP_COMMIT();

    const int NIT = KTOT / 64;   // 16
    for (int it = 0; it < NIT; it++) {
        CP_WAIT1();
        __syncthreads();
        if (it + 2 < NIT)
            gemm_load_stage(smb, (it + 2) % GSTG, (it + 2) * 64, m0, n0, tid);
        CP_COMMIT();

        const uint32_t sb = smb + (it % GSTG) * GSTG_BYTES;
        #pragma unroll
        for (int ks = 0; ks < 4; ks++) {
            const uint32_t koff = (ks * 2 + (lane >> 4)) * 16;
            uint32_t a[4][4], b[2][4];
            #pragma unroll
            for (int mt = 0; mt < 4; mt++) {
                const int r = wm * 64 + mt * 16 + (lane & 15);
                ldm_x4(a[mt], sb + r * GROWB + koff);
            }
            #pragma unroll
            for (int bt = 0; bt < 2; bt++) {
                const int r = wn * 32 + bt * 16 + (lane & 15);
                ldm_x4(b[bt], sb + GB_OFF + r * GROWB + koff);
            }
            #pragma unroll
            for (int mt = 0; mt < 4; mt++)
                #pragma unroll
                for (int nt = 0; nt < 4; nt++) {
                    const int bt = nt >> 1, sub = nt & 1;
                    mma16816(acc[mt][nt], a[mt], b[bt][sub], b[bt][sub + 2]);
                }
        }
    }

    // ---- Epilogue: smem restage per warp, then coalesced global stores ----
    __syncthreads();

    const int seg   = (n0 + wn * 32) >> 6;
    const int hh    = seg / 3;
    const int which = seg % 3;
    const int dh0   = (wn & 1) * 32;
    const int bi    = m0 >> 11;
    const int si0   = (m0 & 2047) + wm * 64;
    const int bh    = bi * HH + hh;
    char* ep = sm + wid * EPW;
    const float scl = (which == 0) ? QSCALE : 1.0f;

    if (which != 2) {
        #pragma unroll
        for (int nt = 0; nt < 4; nt++) {
            const int c = (nt >> 1) * 16 + (nt & 1) * 8 + 2 * (lane & 3);
            const float2 bb = *(const float2*)(bias + n0 + wn * 32 + c);
            #pragma unroll
            for (int mt = 0; mt < 4; mt++)
                #pragma unroll
                for (int rr = 0; rr < 2; rr++) {
                    const int r = mt * 16 + (lane >> 2) + rr * 8;
                    const float vx = (acc[mt][nt][rr * 2 + 0] + bb.x) * scl;
                    const float vy = (acc[mt][nt][rr * 2 + 1] + bb.y) * scl;
                    *(uint32_t*)(ep + r * 72 + c * 2) = packhf(vy, vx);
                }
        }
        __syncwarp();
        __half* dstb = ((which == 0) ? g_Qh : g_Kh)
                     + ((size_t)bh * SS + si0) * DHH + dh0;
        #pragma unroll
        for (int p = 0; p < 16; p++) {
            const int slot = p * 32 + lane;
            const int r = slot >> 3, ch = slot & 7;
            float2 v = *(float2*)(ep + r * 72 + ch * 8);
            *(float2*)(dstb + (size_t)r * DHH + ch * 4) = v;
        }
    } else {
        #pragma unroll
        for (int nt = 0; nt < 4; nt++) {
            const int c = (nt >> 1) * 16 + (nt & 1) * 8 + 2 * (lane & 3);
            const float2 bb = *(const float2*)(bias + n0 + wn * 32 + c);
            #pragma unroll
            for (int mt = 0; mt < 4; mt++)
                #pragma unroll
                for (int rr = 0; rr < 2; rr++) {
                    const int r = mt * 16 + (lane >> 2) + rr * 8;
                    *(__half*)(ep + c * 136 + r * 2)       = __float2half(acc[mt][nt][rr*2+0] + bb.x);
                    *(__half*)(ep + (c + 1) * 136 + r * 2) = __float2half(acc[mt][nt][rr*2+1] + bb.y);
                }
        }
        __syncwarp();
        __half* dstb = g_Vh + ((size_t)bh * DHH + dh0) * SS + si0;
        #pragma unroll
        for (int p = 0; p < 16; p++) {
            const int slot = p * 32 + lane;
            const int d = slot >> 4, ch = slot & 15;
            float2 v = *(float2*)(ep + d * 136 + ch * 8);
            *(float2*)(dstb + (size_t)d * SS + ch * 4) = v;
        }
    }
}

// ---------------------------------------------------------------------------
// HMMA causal flash attention, fp16, exp2-space softmax (ex2.approx).
// Balanced dual-q-tile CTAs: grid (8, 64); CTA p handles q-tiles {p, 15-p}
// so every CTA does exactly 34 key-tile iterations.
// ---------------------------------------------------------------------------
#define APITCH 144
#define AST 18432   // stage bytes: Kh@0, Vh@9216 (64 rows x 144B)
#define ATT_SMEM (2*AST)  // 36864

__global__ __launch_bounds__(128) void attn_hmma(float* __restrict__ out)
{
    extern __shared__ __align__(16) char sm[];
    const uint32_t smb = smem_u32(sm);
    const int tid = threadIdx.x, lane = tid & 31, w = tid >> 5;
    const int bh = blockIdx.y;
    const int tg = lane & 3, g = lane >> 2;
    const int b = bh >> 4, h = bh & 15;

    const __half* khb = g_Kh + (size_t)bh * SS * DHH;
    const __half* vhb = g_Vh + (size_t)bh * DHH * SS;

    #pragma unroll 1
    for (int segi = 0; segi < 2; segi++) {
        const int qt = segi ? (15 - (int)blockIdx.x) : (int)blockIdx.x;
        const int q0 = qt * 128;

        __syncthreads();   // prior segment's smem reads complete
        // --- stage Q tile, then ldmatrix into regs ---
        {
            const __half* qhg = g_Qh + ((size_t)bh * SS + q0) * DHH;
            #pragma unroll
            for (int i = 0; i < 8; i++) {
                const int idx = i * 128 + tid;
                const int row = idx >> 3, c = idx & 7;
                *(float4*)(sm + row * APITCH + c * 16) = *(const float4*)(qhg + row * 64 + c * 8);
            }
        }
        __syncthreads();
        uint32_t qh[2][4][4];
        #pragma unroll
        for (int mt = 0; mt < 2; mt++)
            #pragma unroll
            for (int kc = 0; kc < 4; kc++)
                ldm_x4(qh[mt][kc], smb + (w * 32 + mt * 16 + (lane & 15)) * APITCH
                                  + (kc * 2 + (lane >> 4)) * 16);
        __syncthreads();

        float o[2][8][4];
        #pragma unroll
        for (int mt = 0; mt < 2; mt++)
            #pragma unroll
            for (int nt = 0; nt < 8; nt++)
                #pragma unroll
                for (int e = 0; e < 4; e++) o[mt][nt][e] = 0.0f;
        float mrow[2][2] = {{-1e30f, -1e30f}, {-1e30f, -1e30f}};
        float lrow[2][2] = {{0.f, 0.f}, {0.f, 0.f}};

        const int nkt = qt * 2 + 2;

        // preload tile 0
        #pragma unroll
        for (int i = 0; i < 4; i++) {
            const int idx = i * 128 + tid;
            const int row = idx >> 3, c = idx & 7;
            cp16(smb + row * APITCH + c * 16,        khb + row * 64 + c * 8);
            cp16(smb + 9216 + row * APITCH + c * 16, vhb + (size_t)row * SS + c * 8);
        }
        CP_COMMIT();

        #pragma unroll 1
        for (int jt = 0; jt < nkt; jt++) {
            CP_WAIT0();
            __syncthreads();
            if (jt + 1 < nkt) {
                const uint32_t base = smb + ((jt + 1) & 1) * AST;
                const int j1 = (jt + 1) * 64;
                #pragma unroll
                for (int i = 0; i < 4; i++) {
                    const int idx = i * 128 + tid;
                    const int row = idx >> 3, c = idx & 7;
                    cp16(base + row * APITCH + c * 16,        khb + (size_t)(j1 + row) * 64 + c * 8);
                    cp16(base + 9216 + row * APITCH + c * 16, vhb + (size_t)row * SS + j1 + c * 8);
                }
            }
            CP_COMMIT();

            const uint32_t kb = smb + (jt & 1) * AST;
            const int j0 = jt * 64;

            // ---- S = Q K^T (already in log2 units via Q pre-scale) ----
            float s2[2][8][4];
            #pragma unroll
            for (int mt = 0; mt < 2; mt++)
                #pragma unroll
                for (int nt = 0; nt < 8; nt++)
                    #pragma unroll
                    for (int e = 0; e < 4; e++) s2[mt][nt][e] = 0.0f;

            #pragma unroll
            for (int kc = 0; kc < 4; kc++) {
                uint32_t bf[4][4];
                #pragma unroll
                for (int bt = 0; bt < 4; bt++)
                    ldm_x4(bf[bt], kb + (bt * 16 + (lane & 15)) * APITCH
                                 + (kc * 2 + (lane >> 4)) * 16);
                #pragma unroll
                for (int mt = 0; mt < 2; mt++)
                    #pragma unroll
                    for (int nt = 0; nt < 8; nt++)
                        mma16816(s2[mt][nt], qh[mt][kc], bf[nt >> 1][nt & 1], bf[nt >> 1][(nt & 1) + 2]);
            }

            // ---- mask + online softmax (exp2 space) ----
            const bool need_mask = (j0 + 63 > q0 + w * 32);
            #pragma unroll
            for (int mt = 0; mt < 2; mt++) {
                #pragma unroll
                for (int rs = 0; rs < 2; rs++) {
                    const int row = q0 + w * 32 + mt * 16 + g + rs * 8;
                    if (need_mask) {
                        #pragma unroll
                        for (int nt = 0; nt < 8; nt++)
                            #pragma unroll
                            for (int e = 0; e < 2; e++) {
                                const int key = j0 + nt * 8 + tg * 2 + e;
                                if (key > row) s2[mt][nt][rs * 2 + e] = -1e30f;
                            }
                    }
                    float mx = -1e30f;
                    #pragma unroll
                    for (int nt = 0; nt < 8; nt++)
                        mx = fmaxf(mx, fmaxf(s2[mt][nt][rs * 2], s2[mt][nt][rs * 2 + 1]));
                    mx = fmaxf(mx, __shfl_xor_sync(0xffffffffu, mx, 1));
                    mx = fmaxf(mx, __shfl_xor_sync(0xffffffffu, mx, 2));
                    const float mn = fmaxf(mrow[mt][rs], mx);
                    const float sc = ex2f(mrow[mt][rs] - mn);
                    mrow[mt][rs] = mn;
                    float ps = 0.0f;
                    #pragma unroll
                    for (int nt = 0; nt < 8; nt++) {
                        float p0 = ex2f(s2[mt][nt][rs * 2]     - mn);
                        float p1 = ex2f(s2[mt][nt][rs * 2 + 1] - mn);
                        s2[mt][nt][rs * 2] = p0; s2[mt][nt][rs * 2 + 1] = p1;
                        ps += p0 + p1;
                        o[mt][nt][rs * 2] *= sc; o[mt][nt][rs * 2 + 1] *= sc;
                    }
                    lrow[mt][rs] = lrow[mt][rs] * sc + ps;
                }
            }

            // ---- O += P V ----
            #pragma unroll
            for (int kc = 0; kc < 4; kc++) {
                uint32_t bf[4][4];
                #pragma unroll
                for (int bt = 0; bt < 4; bt++)
                    ldm_x4(bf[bt], kb + 9216 + (bt * 16 + (lane & 15)) * APITCH
                                 + (kc * 2 + (lane >> 4)) * 16);
                #pragma unroll
                for (int mt = 0; mt < 2; mt++) {
                    uint32_t a[4];
                    a[0] = packhf(s2[mt][2*kc][1],   s2[mt][2*kc][0]);
                    a[1] = packhf(s2[mt][2*kc][3],   s2[mt][2*kc][2]);
                    a[2] = packhf(s2[mt][2*kc+1][1], s2[mt][2*kc+1][0]);
                    a[3] = packhf(s2[mt][2*kc+1][3], s2[mt][2*kc+1][2]);
                    #pragma unroll
                    for (int nt = 0; nt < 8; nt++)
                        mma16816(o[mt][nt], a, bf[nt >> 1][nt & 1], bf[nt >> 1][(nt & 1) + 2]);
                }
            }
        }

        // ---- finalize: normalize, write out[b, s, h*64+dh] ----
        #pragma unroll
        for (int mt = 0; mt < 2; mt++) {
            float l0 = lrow[mt][0];
            l0 += __shfl_xor_sync(0xffffffffu, l0, 1);
            l0 += __shfl_xor_sync(0xffffffffu, l0, 2);
            float l1 = lrow[mt][1];
            l1 += __shfl_xor_sync(0xffffffffu, l1, 1);
            l1 += __shfl_xor_sync(0xffffffffu, l1, 2);
            const float i0 = 1.0f / l0, i1 = 1.0f / l1;
            const int row = q0 + w * 32 + mt * 16 + g;
            #pragma unroll
            for (int nt = 0; nt < 8; nt++) {
                const int col = h * 64 + nt * 8 + tg * 2;
                float2 v0 = make_float2(o[mt][nt][0] * i0, o[mt][nt][1] * i0);
                *(float2*)(out + ((size_t)(b * SS + row)) * DD + col) = v0;
                float2 v1 = make_float2(o[mt][nt][2] * i1, o[mt][nt][3] * i1);
                *(float2*)(out + ((size_t)(b * SS + row + 8)) * DD + col) = v1;
            }
        }
    }
}

// ---------------------------------------------------------------------------
extern "C" void kernel_launch(void* const* d_in, const int* in_sizes, int n_in,
                              void* d_out, int out_size)
{
    const float* x    = (const float*)d_in[0];   // [B,S,D]
    const float* W    = (const float*)d_in[1];   // [D,3D]
    const float* bias = (const float*)d_in[2];   // [3D]
    float* out        = (float*)d_out;           // [B,S,D]

    cudaFuncSetAttribute(qkv_gemm_hmma, cudaFuncAttributeMaxDynamicSharedMemorySize, GEMM_SMEM);
    cudaFuncSetAttribute(attn_hmma,     cudaFuncAttributeMaxDynamicSharedMemorySize, ATT_SMEM);

    conv_fused<<<4096 + 3072, 256>>>(x, W);

    dim3 gemm_grid(NTOT / 128, MTOT / 128);   // (24, 64)
    qkv_gemm_hmma<<<gemm_grid, 256, GEMM_SMEM>>>(bias);

    dim3 attn_grid(8, BB * HH);               // (8, 64), dual q-tiles per CTA
    attn_hmma<<<attn_grid, 128, ATT_SMEM>>>(out);
}

// round 10
// speedup vs baseline: 1.2743x; 1.0298x over previous
#include <cuda_runtime.h>
#include <cuda_fp16.h>
#include <cstdint>

// Problem constants
#define BB 4
#define SS 2048
#define DD 1024
#define HH 16
#define DHH 64
#define MTOT (BB*SS)     // 8192
#define NTOT (3*DD)      // 3072
#define KTOT (DD)        // 1024

#define QKVN ((size_t)BB*HH*SS*DHH)

// Q pre-scale: 1/sqrt(64) * log2(e)  (softmax done in exp2 space)
#define QSCALE 0.1803368801111204f

// Scratch: fp16 single-precision-pass operands
__device__ __align__(16) __half g_A[(size_t)MTOT*KTOT];   // x   [M, K] K-major
__device__ __align__(16) __half g_B[(size_t)NTOT*KTOT];   // W^T [N, K] K-major
__device__ __align__(16) __half g_Qh[QKVN];               // [B,H,S,64] (pre-scaled)
__device__ __align__(16) __half g_Kh[QKVN];               // [B,H,S,64]
__device__ __align__(16) __half g_Vh[QKVN];               // [B,H,64,S] (transposed)

// ---------------------------------------------------------------------------
// Helpers (sm_103 baseline-safe: ldmatrix / mma.sync / cp.async only)
// ---------------------------------------------------------------------------
__device__ __forceinline__ uint32_t smem_u32(const void* p) {
    uint32_t a;
    asm("{ .reg .u64 t; cvta.to.shared.u64 t, %1; cvt.u32.u64 %0, t; }" : "=r"(a) : "l"(p));
    return a;
}
__device__ __forceinline__ void ldm_x4(uint32_t* r, uint32_t addr) {
    asm volatile("ldmatrix.sync.aligned.m8n8.x4.shared.b16 {%0,%1,%2,%3}, [%4];"
        : "=r"(r[0]), "=r"(r[1]), "=r"(r[2]), "=r"(r[3]) : "r"(addr));
}
__device__ __forceinline__ void mma16816(float* d, const uint32_t* a, uint32_t b0, uint32_t b1) {
    asm volatile("mma.sync.aligned.m16n8k16.row.col.f32.f16.f16.f32 "
        "{%0,%1,%2,%3}, {%4,%5,%6,%7}, {%8,%9}, {%0,%1,%2,%3};"
        : "+f"(d[0]), "+f"(d[1]), "+f"(d[2]), "+f"(d[3])
        : "r"(a[0]), "r"(a[1]), "r"(a[2]), "r"(a[3]), "r"(b0), "r"(b1));
}
__device__ __forceinline__ void cp16(uint32_t dst, const void* src) {
    asm volatile("cp.async.cg.shared.global [%0], [%1], 16;" :: "r"(dst), "l"(src));
}
#define CP_COMMIT() asm volatile("cp.async.commit_group;" ::: "memory")
#define CP_WAIT1()  asm volatile("cp.async.wait_group 1;" ::: "memory")
#define CP_WAIT0()  asm volatile("cp.async.wait_group 0;" ::: "memory")

__device__ __forceinline__ uint32_t packhf(float e1, float e0) {
    uint32_t r; asm("cvt.rn.f16x2.f32 %0, %1, %2;" : "=r"(r) : "f"(e1), "f"(e0)); return r;
}
__device__ __forceinline__ float ex2f(float x) {
    float y; asm("ex2.approx.ftz.f32 %0, %1;" : "=f"(y) : "f"(x)); return y;
}

// ---------------------------------------------------------------------------
// Fused conversion kernel.
//   blocks [0, 4096):    x [M,K] fp32 -> g_A fp16 (8 elems/thread)
//   blocks [4096, 7168): W [K,N] fp32 -> g_B [N,K] fp16 (32x32 transpose tiles)
// ---------------------------------------------------------------------------
__global__ __launch_bounds__(256) void conv_fused(const float* __restrict__ x,
                                                  const float* __restrict__ W)
{
    if (blockIdx.x < 4096) {
        const int base = (blockIdx.x * 256 + threadIdx.x) * 8;
        float4 v0 = *(const float4*)(x + base);
        float4 v1 = *(const float4*)(x + base + 4);
        __half h[8];
        h[0] = __float2half(v0.x); h[1] = __float2half(v0.y);
        h[2] = __float2half(v0.z); h[3] = __float2half(v0.w);
        h[4] = __float2half(v1.x); h[5] = __float2half(v1.y);
        h[6] = __float2half(v1.z); h[7] = __float2half(v1.w);
        *(float4*)(g_A + base) = *(float4*)h;
    } else {
        __shared__ float T[32][33];
        const int blk = blockIdx.x - 4096;
        const int n0 = (blk % 96) * 32;
        const int k0 = (blk / 96) * 32;
        const int tid = threadIdx.x;
        const int tx = tid & 31, ty = tid >> 5;

        #pragma unroll
        for (int i = 0; i < 4; i++)
            T[ty + i * 8][tx] = W[(size_t)(k0 + ty + i * 8) * NTOT + n0 + tx];
        __syncthreads();

        if (tid < 128) {
            const int nl = tid >> 2;
            const int kq = (tid & 3) * 8;
            __half h[8];
            #pragma unroll
            for (int i = 0; i < 8; i++) h[i] = __float2half(T[kq + i][nl]);
            *(float4*)(g_B + (size_t)(n0 + nl) * KTOT + k0 + kq) = *(float4*)h;
        }
    }
}

// ---------------------------------------------------------------------------
// HMMA GEMM: C[8192,3072] = A @ B^T. CTA 128x128, warp tile 64x32 (2x4 warps),
// BK=64 (pitch 144B), 3-stage cp.async, 2 CTAs/SM.
// Epilogue: smem-restaged coalesced stores -> fp16 Q(xQSCALE)/K/V^T.
// ---------------------------------------------------------------------------
#define GROWB 144
#define GSTG_BYTES (256*GROWB)       // 36864 (A rows 0-127, B rows 128-255)
#define GB_OFF (128*GROWB)           // 18432
#define GSTG 3
#define GEMM_SMEM (GSTG*GSTG_BYTES)  // 110592
#define EPW 5120                     // per-warp epilogue staging region

__device__ __forceinline__ void gemm_load_stage(uint32_t smb, int s, int kc,
                                                int m0, int n0, int tid)
{
    const uint32_t base = smb + s * GSTG_BYTES;
    #pragma unroll
    for (int i = 0; i < 8; i++) {
        const int idx = i * 256 + tid;      // 0..2047
        const int row = idx >> 3, c = idx & 7;
        const __half* src = (row < 128)
            ? g_A + (size_t)(m0 + row) * KTOT + kc + c * 8
            : g_B + (size_t)(n0 + row - 128) * KTOT + kc + c * 8;
        cp16(base + row * GROWB + c * 16, src);
    }
}

__global__ __launch_bounds__(256, 2) void qkv_gemm_hmma(const float* __restrict__ bias)
{
    extern __shared__ __align__(16) char sm[];
    const uint32_t smb = smem_u32(sm);
    const int tid = threadIdx.x, lane = tid & 31, wid = tid >> 5;
    const int m0 = blockIdx.y * 128;
    const int n0 = blockIdx.x * 128;
    const int wm = wid & 1;
    const int wn = wid >> 1;

    float acc[4][4][4];
    #pragma unroll
    for (int i = 0; i < 4; i++)
        #pragma unroll
        for (int j = 0; j < 4; j++)
            #pragma unroll
            for (int r = 0; r < 4; r++) acc[i][j][r] = 0.0f;

    gemm_load_stage(smb, 0, 0,  m0, n0, tid);
    CP_COMMIT();
    gemm_load_stage(smb, 1, 64, m0, n0, tid);
    CP_COMMIT();

    const int NIT = KTOT / 64;   // 16
    for (int it = 0; it < NIT; it++) {
        CP_WAIT1();
        __syncthreads();
        if (it + 2 < NIT)
            gemm_load_stage(smb, (it + 2) % GSTG, (it + 2) * 64, m0, n0, tid);
        CP_COMMIT();

        const uint32_t sb = smb + (it % GSTG) * GSTG_BYTES;
        #pragma unroll
        for (int ks = 0; ks < 4; ks++) {
            const uint32_t koff = (ks * 2 + (lane >> 4)) * 16;
            uint32_t a[4][4], b[2][4];
            #pragma unroll
            for (int mt = 0; mt < 4; mt++) {
                const int r = wm * 64 + mt * 16 + (lane & 15);
                ldm_x4(a[mt], sb + r * GROWB + koff);
            }
            #pragma unroll
            for (int bt = 0; bt < 2; bt++) {
                const int r = wn * 32 + bt * 16 + (lane & 15);
                ldm_x4(b[bt], sb + GB_OFF + r * GROWB + koff);
            }
            #pragma unroll
            for (int mt = 0; mt < 4; mt++)
                #pragma unroll
                for (int nt = 0; nt < 4; nt++) {
                    const int bt = nt >> 1, sub = nt & 1;
                    mma16816(acc[mt][nt], a[mt], b[bt][sub], b[bt][sub + 2]);
                }
        }
    }

    // ---- Epilogue: smem restage per warp, then coalesced global stores ----
    __syncthreads();

    const int seg   = (n0 + wn * 32) >> 6;
    const int hh    = seg / 3;
    const int which = seg % 3;
    const int dh0   = (wn & 1) * 32;
    const int bi    = m0 >> 11;
    const int si0   = (m0 & 2047) + wm * 64;
    const int bh    = bi * HH + hh;
    char* ep = sm + wid * EPW;
    const float scl = (which == 0) ? QSCALE : 1.0f;

    if (which != 2) {
        #pragma unroll
        for (int nt = 0; nt < 4; nt++) {
            const int c = (nt >> 1) * 16 + (nt & 1) * 8 + 2 * (lane & 3);
            const float2 bb = *(const float2*)(bias + n0 + wn * 32 + c);
            #pragma unroll
            for (int mt = 0; mt < 4; mt++)
                #pragma unroll
                for (int rr = 0; rr < 2; rr++) {
                    const int r = mt * 16 + (lane >> 2) + rr * 8;
                    const float vx = (acc[mt][nt][rr * 2 + 0] + bb.x) * scl;
                    const float vy = (acc[mt][nt][rr * 2 + 1] + bb.y) * scl;
                    *(uint32_t*)(ep + r * 72 + c * 2) = packhf(vy, vx);
                }
        }
        __syncwarp();
        __half* dstb = ((which == 0) ? g_Qh : g_Kh)
                     + ((size_t)bh * SS + si0) * DHH + dh0;
        #pragma unroll
        for (int p = 0; p < 16; p++) {
            const int slot = p * 32 + lane;
            const int r = slot >> 3, ch = slot & 7;
            float2 v = *(float2*)(ep + r * 72 + ch * 8);
            *(float2*)(dstb + (size_t)r * DHH + ch * 4) = v;
        }
    } else {
        #pragma unroll
        for (int nt = 0; nt < 4; nt++) {
            const int c = (nt >> 1) * 16 + (nt & 1) * 8 + 2 * (lane & 3);
            const float2 bb = *(const float2*)(bias + n0 + wn * 32 + c);
            #pragma unroll
            for (int mt = 0; mt < 4; mt++)
                #pragma unroll
                for (int rr = 0; rr < 2; rr++) {
                    const int r = mt * 16 + (lane >> 2) + rr * 8;
                    *(__half*)(ep + c * 136 + r * 2)       = __float2half(acc[mt][nt][rr*2+0] + bb.x);
                    *(__half*)(ep + (c + 1) * 136 + r * 2) = __float2half(acc[mt][nt][rr*2+1] + bb.y);
                }
        }
        __syncwarp();
        __half* dstb = g_Vh + ((size_t)bh * DHH + dh0) * SS + si0;
        #pragma unroll
        for (int p = 0; p < 16; p++) {
            const int slot = p * 32 + lane;
            const int d = slot >> 4, ch = slot & 15;
            float2 v = *(float2*)(ep + d * 136 + ch * 8);
            *(float2*)(dstb + (size_t)d * SS + ch * 4) = v;
        }
    }
}

// ---------------------------------------------------------------------------
// HMMA causal flash attention, fp16, exp2-space softmax (ex2.approx).
// CTA: 64 q rows, 4 warps x 16 rows (low reg pressure -> 3 CTAs/SM).
// Balanced dual-q-tile CTAs: grid (16, 64); CTA p handles q-tiles {p, 31-p}
// = exactly 33 key-tile iterations each.
// ---------------------------------------------------------------------------
#define APITCH 144
#define AST 18432   // stage bytes: Kh@0, Vh@9216 (64 rows x 144B)
#define ATT_SMEM (2*AST)  // 36864

__global__ __launch_bounds__(128, 3) void attn_hmma(float* __restrict__ out)
{
    extern __shared__ __align__(16) char sm[];
    const uint32_t smb = smem_u32(sm);
    const int tid = threadIdx.x, lane = tid & 31, w = tid >> 5;
    const int bh = blockIdx.y;
    const int tg = lane & 3, g = lane >> 2;
    const int b = bh >> 4, h = bh & 15;

    const __half* khb = g_Kh + (size_t)bh * SS * DHH;
    const __half* vhb = g_Vh + (size_t)bh * DHH * SS;

    #pragma unroll 1
    for (int segi = 0; segi < 2; segi++) {
        const int qt = segi ? (31 - (int)blockIdx.x) : (int)blockIdx.x;
        const int q0 = qt * 64;

        __syncthreads();   // prior segment's smem reads complete
        // --- stage Q tile (64 rows), then ldmatrix into regs ---
        {
            const __half* qhg = g_Qh + ((size_t)bh * SS + q0) * DHH;
            #pragma unroll
            for (int i = 0; i < 4; i++) {
                const int idx = i * 128 + tid;
                const int row = idx >> 3, c = idx & 7;
                *(float4*)(sm + row * APITCH + c * 16) = *(const float4*)(qhg + row * 64 + c * 8);
            }
        }
        __syncthreads();
        uint32_t qh[4][4];
        #pragma unroll
        for (int kc = 0; kc < 4; kc++)
            ldm_x4(qh[kc], smb + (w * 16 + (lane & 15)) * APITCH
                          + (kc * 2 + (lane >> 4)) * 16);
        __syncthreads();

        float o[8][4];
        #pragma unroll
        for (int nt = 0; nt < 8; nt++)
            #pragma unroll
            for (int e = 0; e < 4; e++) o[nt][e] = 0.0f;
        float mrow[2] = {-1e30f, -1e30f};
        float lrow[2] = {0.f, 0.f};

        const int nkt = qt + 1;

        // preload tile 0
        #pragma unroll
        for (int i = 0; i < 4; i++) {
            const int idx = i * 128 + tid;
            const int row = idx >> 3, c = idx & 7;
            cp16(smb + row * APITCH + c * 16,        khb + row * 64 + c * 8);
            cp16(smb + 9216 + row * APITCH + c * 16, vhb + (size_t)row * SS + c * 8);
        }
        CP_COMMIT();

        #pragma unroll 1
        for (int jt = 0; jt < nkt; jt++) {
            CP_WAIT0();
            __syncthreads();
            if (jt + 1 < nkt) {
                const uint32_t base = smb + ((jt + 1) & 1) * AST;
                const int j1 = (jt + 1) * 64;
                #pragma unroll
                for (int i = 0; i < 4; i++) {
                    const int idx = i * 128 + tid;
                    const int row = idx >> 3, c = idx & 7;
                    cp16(base + row * APITCH + c * 16,        khb + (size_t)(j1 + row) * 64 + c * 8);
                    cp16(base + 9216 + row * APITCH + c * 16, vhb + (size_t)row * SS + j1 + c * 8);
                }
            }
            CP_COMMIT();

            const uint32_t kb = smb + (jt & 1) * AST;
            const int j0 = jt * 64;

            // ---- S = Q K^T (already in log2 units via Q pre-scale) ----
            float s2[8][4];
            #pragma unroll
            for (int nt = 0; nt < 8; nt++)
                #pragma unroll
                for (int e = 0; e < 4; e++) s2[nt][e] = 0.0f;

            #pragma unroll
            for (int kc = 0; kc < 4; kc++) {
                uint32_t bf[4][4];
                #pragma unroll
                for (int bt = 0; bt < 4; bt++)
                    ldm_x4(bf[bt], kb + (bt * 16 + (lane & 15)) * APITCH
                                 + (kc * 2 + (lane >> 4)) * 16);
                #pragma unroll
                for (int nt = 0; nt < 8; nt++)
                    mma16816(s2[nt], qh[kc], bf[nt >> 1][nt & 1], bf[nt >> 1][(nt & 1) + 2]);
            }

            // ---- mask + online softmax (exp2 space) ----
            const bool need_mask = (j0 + 63 > q0 + w * 16);
            #pragma unroll
            for (int rs = 0; rs < 2; rs++) {
                const int row = q0 + w * 16 + g + rs * 8;
                if (need_mask) {
                    #pragma unroll
                    for (int nt = 0; nt < 8; nt++)
                        #pragma unroll
                        for (int e = 0; e < 2; e++) {
                            const int key = j0 + nt * 8 + tg * 2 + e;
                            if (key > row) s2[nt][rs * 2 + e] = -1e30f;
                        }
                }
                float mx = -1e30f;
                #pragma unroll
                for (int nt = 0; nt < 8; nt++)
                    mx = fmaxf(mx, fmaxf(s2[nt][rs * 2], s2[nt][rs * 2 + 1]));
                mx = fmaxf(mx, __shfl_xor_sync(0xffffffffu, mx, 1));
                mx = fmaxf(mx, __shfl_xor_sync(0xffffffffu, mx, 2));
                const float mn = fmaxf(mrow[rs], mx);
                const float sc = ex2f(mrow[rs] - mn);
                mrow[rs] = mn;
                float ps = 0.0f;
                #pragma unroll
                for (int nt = 0; nt < 8; nt++) {
                    float p0 = ex2f(s2[nt][rs * 2]     - mn);
                    float p1 = ex2f(s2[nt][rs * 2 + 1] - mn);
                    s2[nt][rs * 2] = p0; s2[nt][rs * 2 + 1] = p1;
                    ps += p0 + p1;
                    o[nt][rs * 2] *= sc; o[nt][rs * 2 + 1] *= sc;
                }
                lrow[rs] = lrow[rs] * sc + ps;
            }

            // ---- O += P V ----
            #pragma unroll
            for (int kc = 0; kc < 4; kc++) {
                uint32_t bf[4][4];
                #pragma unroll
                for (int bt = 0; bt < 4; bt++)
                    ldm_x4(bf[bt], kb + 9216 + (bt * 16 + (lane & 15)) * APITCH
                                 + (kc * 2 + (lane >> 4)) * 16);
                uint32_t a[4];
                a[0] = packhf(s2[2*kc][1],   s2[2*kc][0]);
                a[1] = packhf(s2[2*kc][3],   s2[2*kc][2]);
                a[2] = packhf(s2[2*kc+1][1], s2[2*kc+1][0]);
                a[3] = packhf(s2[2*kc+1][3], s2[2*kc+1][2]);
                #pragma unroll
                for (int nt = 0; nt < 8; nt++)
                    mma16816(o[nt], a, bf[nt >> 1][nt & 1], bf[nt >> 1][(nt & 1) + 2]);
            }
        }

        // ---- finalize: normalize, write out[b, s, h*64+dh] ----
        float l0 = lrow[0];
        l0 += __shfl_xor_sync(0xffffffffu, l0, 1);
        l0 += __shfl_xor_sync(0xffffffffu, l0, 2);
        float l1 = lrow[1];
        l1 += __shfl_xor_sync(0xffffffffu, l1, 1);
        l1 += __shfl_xor_sync(0xffffffffu, l1, 2);
        const float i0 = 1.0f / l0, i1 = 1.0f / l1;
        const int row = q0 + w * 16 + g;
        #pragma unroll
        for (int nt = 0; nt < 8; nt++) {
            const int col = h * 64 + nt * 8 + tg * 2;
            float2 v0 = make_float2(o[nt][0] * i0, o[nt][1] * i0);
            *(float2*)(out + ((size_t)(b * SS + row)) * DD + col) = v0;
            float2 v1 = make_float2(o[nt][2] * i1, o[nt][3] * i1);
            *(float2*)(out + ((size_t)(b * SS + row + 8)) * DD + col) = v1;
        }
    }
}

// ---------------------------------------------------------------------------
extern "C" void kernel_launch(void* const* d_in, const int* in_sizes, int n_in,
                              void* d_out, int out_size)
{
    const float* x    = (const float*)d_in[0];   // [B,S,D]
    const float* W    = (const float*)d_in[1];   // [D,3D]
    const float* bias = (const float*)d_in[2];   // [3D]
    float* out        = (float*)d_out;           // [B,S,D]

    cudaFuncSetAttribute(qkv_gemm_hmma, cudaFuncAttributeMaxDynamicSharedMemorySize, GEMM_SMEM);
    cudaFuncSetAttribute(attn_hmma,     cudaFuncAttributeMaxDynamicSharedMemorySize, ATT_SMEM);

    conv_fused<<<4096 + 3072, 256>>>(x, W);

    dim3 gemm_grid(NTOT / 128, MTOT / 128);   // (24, 64)
    qkv_gemm_hmma<<<gemm_grid, 256, GEMM_SMEM>>>(bias);

    dim3 attn_grid(16, BB * HH);              // (16, 64), dual q-tiles per CTA
    attn_hmma<<<attn_grid, 128, ATT_SMEM>>>(out);
}